// round 3
// baseline (speedup 1.0000x reference)
#include <cuda_runtime.h>
#include <cstdint>

// GRU dims
#define Bdim  128
#define Tdim  512
#define Idim  512
#define Hdim  1024
#define G3    3072          // 3*H
#define MTOT  65536         // B*T
#define NCTA  128           // persistent CTAs (<= 148 SMs, all co-resident)

// Scratch (static __device__ — no allocations allowed)
__device__ float g_fi[(size_t)MTOT * G3];     // from_input: [B*T, 3H]
__device__ unsigned g_bar[Tdim];              // one barrier slot per step

// ---------- packed fp32x2 FMA helpers ----------
__device__ __forceinline__ void ffma2(unsigned long long& d,
                                      unsigned long long a,
                                      unsigned long long b) {
  asm("fma.rn.f32x2 %0, %1, %2, %0;" : "+l"(d) : "l"(a), "l"(b));
}
__device__ __forceinline__ unsigned long long dup2(float a) {
  unsigned long long u;
  asm("mov.b64 %0, {%1, %2};" : "=l"(u) : "f"(a), "f"(a));
  return u;
}

union alignas(16) Acc8 {
  unsigned long long u[4];
  float f[8];
  float4 v[2];
};
union alignas(16) V8 {
  float4 v[2];
  unsigned long long u[4];
  float f[8];
};
union U2 { unsigned long long u; float f[2]; };

__device__ __forceinline__ float sigmoidf_fast(float x) {
  return 1.0f / (1.0f + __expf(-x));
}

// release-add and acquire-load for the grid barrier
__device__ __forceinline__ void bar_arrive(unsigned* p) {
  asm volatile("red.release.gpu.global.add.u32 [%0], 1;" :: "l"(p) : "memory");
}
__device__ __forceinline__ unsigned bar_peek(const unsigned* p) {
  unsigned v;
  asm volatile("ld.acquire.gpu.global.u32 %0, [%1];" : "=r"(v) : "l"(p) : "memory");
  return v;
}

// =====================================================================
// Reset barrier slots (graph node #1)
// =====================================================================
__global__ void reset_kernel() {
  g_bar[threadIdx.x] = 0u;
}

// =====================================================================
// Phase A: g_fi[m, n] = inputs[m, :] @ W_from_in[:, n] + bias[n]
//   M=65536, K=512, N=3072.  Tile 128x128, BK=16, 256 threads, 8x8/thread.
// =====================================================================
__global__ void __launch_bounds__(256) gemm_fi_kernel(
    const float* __restrict__ A,      // [MTOT, Idim]
    const float* __restrict__ W,      // [Idim, G3]
    const float* __restrict__ bias)   // [6H], uses [0:3H)
{
  __shared__ float As[16][128];       // transposed: As[k][m]
  __shared__ float Bs[16][128];       // Bs[k][n]
  const int tid = threadIdx.x;
  const int tx = tid & 15;
  const int ty = tid >> 4;
  const int bm = blockIdx.y * 128;
  const int bn = blockIdx.x * 128;

  Acc8 acc[8];
#pragma unroll
  for (int i = 0; i < 8; i++)
#pragma unroll
    for (int j = 0; j < 4; j++) acc[i].u[j] = 0ULL;

  for (int k0 = 0; k0 < Idim; k0 += 16) {
#pragma unroll
    for (int l = 0; l < 2; l++) {     // A tile: 128x16 = 512 float4
      int idx = tid + l * 256;
      int row = idx >> 2;
      int kq  = (idx & 3) << 2;
      float4 v = *(const float4*)(A + (size_t)(bm + row) * Idim + k0 + kq);
      As[kq + 0][row] = v.x; As[kq + 1][row] = v.y;
      As[kq + 2][row] = v.z; As[kq + 3][row] = v.w;
    }
#pragma unroll
    for (int l = 0; l < 2; l++) {     // W tile: 16x128 = 512 float4
      int idx = tid + l * 256;
      int row = idx >> 5;
      int nq  = (idx & 31) << 2;
      *(float4*)&Bs[row][nq] = *(const float4*)(W + (size_t)(k0 + row) * G3 + bn + nq);
    }
    __syncthreads();
#pragma unroll
    for (int k = 0; k < 16; k++) {
      V8 a, b;
      a.v[0] = *(const float4*)&As[k][ty * 8];
      a.v[1] = *(const float4*)&As[k][ty * 8 + 4];
      b.v[0] = *(const float4*)&Bs[k][tx * 8];
      b.v[1] = *(const float4*)&Bs[k][tx * 8 + 4];
#pragma unroll
      for (int i = 0; i < 8; i++) {
        unsigned long long ap = dup2(a.f[i]);
#pragma unroll
        for (int j = 0; j < 4; j++) ffma2(acc[i].u[j], ap, b.u[j]);
      }
    }
    __syncthreads();
  }

  V8 bv;
  bv.v[0] = *(const float4*)(bias + bn + tx * 8);
  bv.v[1] = *(const float4*)(bias + bn + tx * 8 + 4);
#pragma unroll
  for (int i = 0; i < 8; i++) {
#pragma unroll
    for (int j = 0; j < 8; j++) acc[i].f[j] += bv.f[j];
    float* Crow = g_fi + (size_t)(bm + ty * 8 + i) * G3 + bn + tx * 8;
    *(float4*)Crow       = acc[i].v[0];
    *(float4*)(Crow + 4) = acc[i].v[1];
  }
}

// =====================================================================
// Persistent recurrence kernel (graph node #3).
//   Grid: 128 CTAs x 128 threads. CTA c owns h in [8c, 8c+8), all batches.
//   Per step: GEMM h_{t-1}[128x1024] @ Wh_slice[1024 x 24] (24 = 3 gates x 8 h),
//   gates in-register, write h_t, grid barrier.
//   FFMA2 pairs over K: acc.lo/.hi hold even/odd-k partials, summed at the end.
// =====================================================================
__global__ void __launch_bounds__(128, 1) recurrence_kernel(
    const float* __restrict__ Wh,     // [Hdim, G3]
    const float* __restrict__ bias,   // [6H]
    float* __restrict__ out)          // d_out: hseq [B,T,H] then h_last [B,H]
{
  __shared__ float As[Bdim][36];      // h_prev tile: [b][k], BK=32, pad->36
  __shared__ float Ws2[24][34];       // W slice transposed: [n][k], pad->34

  const int tid = threadIdx.x;
  const int tx  = tid & 7;            // h within slice
  const int ty  = tid >> 3;           // 16 groups of 8 batches
  const int c   = blockIdx.x;
  const int h   = c * 8 + tx;
  const int b0  = ty * 8;

  // bias_h for this h (constant across steps and batches)
  float bh[3];
#pragma unroll
  for (int g = 0; g < 3; g++) bh[g] = bias[G3 + g * Hdim + h];

  // h state resident in registers: rows b0..b0+7, column h
  float hreg[8];
#pragma unroll
  for (int i = 0; i < 8; i++) hreg[i] = 0.0f;

  for (int t = 0; t < Tdim; t++) {
    // Prefetch from_input values for this step (hoisted LDGs, latency hidden by GEMM)
    float fi[8][3];
#pragma unroll
    for (int i = 0; i < 8; i++) {
      const size_t base = ((size_t)(b0 + i) * Tdim + t) * G3;
#pragma unroll
      for (int g = 0; g < 3; g++) fi[i][g] = __ldg(&g_fi[base + g * Hdim + h]);
    }

    U2 acc[8][3];
#pragma unroll
    for (int i = 0; i < 8; i++)
#pragma unroll
      for (int g = 0; g < 3; g++) acc[i][g].u = 0ULL;

    if (t > 0) {
      const float* hprev = out + (size_t)(t - 1) * Hdim;  // + b*T*H per row

      for (int kb = 0; kb < Hdim; kb += 32) {
        // --- stage h_prev tile: 128 b x 32 k = 1024 float4, 8 per thread ---
        float4 av[8];
#pragma unroll
        for (int l = 0; l < 8; l++) {
          int idx = tid + l * 128;
          int b   = idx >> 3;
          int kq  = (idx & 7) << 2;
          av[l] = *(const float4*)(hprev + (size_t)b * (Tdim * Hdim) + kb + kq);
        }
        // --- stage W slice (transposed): 32 k x 24 n = 192 float4 ---
        float4 wv[2]; int wk[2], wn[2];
#pragma unroll
        for (int l = 0; l < 2; l++) {
          int f4 = tid + l * 128;
          wk[l] = -1;
          if (f4 < 192) {
            int k    = f4 / 6;
            int rem  = f4 - k * 6;
            int g    = rem >> 1;
            int half = rem & 1;
            wk[l] = k;
            wn[l] = g * 8 + half * 4;
            wv[l] = *(const float4*)(Wh + (size_t)(kb + k) * G3 + g * Hdim + c * 8 + half * 4);
          }
        }
        if (kb) __syncthreads();      // protect smem reuse (kb==0 safe: after barrier)
#pragma unroll
        for (int l = 0; l < 8; l++) {
          int idx = tid + l * 128;
          int b   = idx >> 3;
          int kq  = (idx & 7) << 2;
          *(float4*)&As[b][kq] = av[l];
        }
#pragma unroll
        for (int l = 0; l < 2; l++) {
          if (wk[l] >= 0) {
            Ws2[wn[l] + 0][wk[l]] = wv[l].x;
            Ws2[wn[l] + 1][wk[l]] = wv[l].y;
            Ws2[wn[l] + 2][wk[l]] = wv[l].z;
            Ws2[wn[l] + 3][wk[l]] = wv[l].w;
          }
        }
        __syncthreads();

        // --- compute: 16 k-pairs, 24 ffma2 each ---
#pragma unroll 4
        for (int kp = 0; kp < 16; kp++) {
          unsigned long long w2[3];
#pragma unroll
          for (int g = 0; g < 3; g++)
            w2[g] = *(const unsigned long long*)&Ws2[g * 8 + tx][2 * kp];
#pragma unroll
          for (int i = 0; i < 8; i++) {
            unsigned long long a2 = *(const unsigned long long*)&As[b0 + i][2 * kp];
            ffma2(acc[i][0].u, a2, w2[0]);
            ffma2(acc[i][1].u, a2, w2[1]);
            ffma2(acc[i][2].u, a2, w2[2]);
          }
        }
      }
    }

    // --- gates (in-register) + write h_t ---
#pragma unroll
    for (int i = 0; i < 8; i++) {
      float hr = acc[i][0].f[0] + acc[i][0].f[1] + bh[0];
      float hz = acc[i][1].f[0] + acc[i][1].f[1] + bh[1];
      float hn = acc[i][2].f[0] + acc[i][2].f[1] + bh[2];
      float r = sigmoidf_fast(fi[i][0] + hr);
      float z = sigmoidf_fast(fi[i][1] + hz);
      float n = tanhf(fi[i][2] + r * hn);
      hreg[i] = (1.0f - z) * n + z * hreg[i];
      out[((size_t)(b0 + i) * Tdim + t) * Hdim + h] = hreg[i];
    }

    // --- grid barrier (skip after last step) ---
    if (t < Tdim - 1) {
      __syncthreads();
      if (tid == 0) {
        bar_arrive(&g_bar[t]);
        while (bar_peek(&g_bar[t]) < NCTA) { __nanosleep(64); }
      }
      __syncthreads();
    }
  }

  // h_last tail of d_out
#pragma unroll
  for (int i = 0; i < 8; i++)
    out[(size_t)Bdim * Tdim * Hdim + (size_t)(b0 + i) * Hdim + h] = hreg[i];
}

// =====================================================================
extern "C" void kernel_launch(void* const* d_in, const int* in_sizes, int n_in,
                              void* d_out, int out_size) {
  (void)in_sizes; (void)n_in; (void)out_size;
  const float* inputs = (const float*)d_in[0];   // [B, T, I]
  const float* W_in   = (const float*)d_in[1];   // [I, 3H]
  const float* W_h    = (const float*)d_in[2];   // [H, 3H]
  const float* bias   = (const float*)d_in[3];   // [6H]
  float* out = (float*)d_out;

  reset_kernel<<<1, Tdim>>>();

  {
    dim3 grid(G3 / 128, MTOT / 128);             // (24, 512)
    gemm_fi_kernel<<<grid, 256>>>(inputs, W_in, bias);
  }

  recurrence_kernel<<<NCTA, 128>>>(W_h, bias, out);
}

// round 7
// speedup vs baseline: 1.3808x; 1.3808x over previous
#include <cuda_runtime.h>
#include <cstdint>

// GRU dims
#define Bdim  128
#define Tdim  512
#define Idim  512
#define Hdim  1024
#define G3    3072          // 3*H
#define MTOT  65536         // B*T
#define NCTA  128           // persistent CTAs (<=148 SMs, all co-resident)

#define WPAD  1026          // Ws row stride (floats): 1026 % 32 == 2 -> conflict-free
#define WS_FLOATS (24 * WPAD)
#define AS_FLOATS (2 * Bdim * 32)
#define SMEM_BYTES ((WS_FLOATS + AS_FLOATS) * 4)

// Scratch (static __device__ — no allocations allowed)
__device__ float g_fi[(size_t)MTOT * G3];     // from_input: [B*T, 3H]
__device__ unsigned g_bar[Tdim];              // one barrier slot per step

// ---------- packed fp32x2 FMA helpers ----------
__device__ __forceinline__ void ffma2(unsigned long long& d,
                                      unsigned long long a,
                                      unsigned long long b) {
  asm("fma.rn.f32x2 %0, %1, %2, %0;" : "+l"(d) : "l"(a), "l"(b));
}
__device__ __forceinline__ unsigned long long dup2(float a) {
  unsigned long long u;
  asm("mov.b64 %0, {%1, %2};" : "=l"(u) : "f"(a), "f"(a));
  return u;
}

union alignas(16) Acc8 {
  unsigned long long u[4];
  float f[8];
  float4 v[2];
};
union alignas(16) V8 {
  float4 v[2];
  unsigned long long u[4];
  float f[8];
};
union U2 { unsigned long long u; float f[2]; };

__device__ __forceinline__ float sigmoidf_fast(float x) {
  return 1.0f / (1.0f + __expf(-x));
}

// release-add and acquire-load for the grid barrier
__device__ __forceinline__ void bar_arrive(unsigned* p) {
  asm volatile("red.release.gpu.global.add.u32 [%0], 1;" :: "l"(p) : "memory");
}
__device__ __forceinline__ unsigned bar_peek(const unsigned* p) {
  unsigned v;
  asm volatile("ld.acquire.gpu.global.u32 %0, [%1];" : "=r"(v) : "l"(p) : "memory");
  return v;
}

// =====================================================================
// Reset barrier slots (graph node #1)
// =====================================================================
__global__ void reset_kernel() {
  g_bar[threadIdx.x] = 0u;
}

// =====================================================================
// Phase A: g_fi[m, n] = inputs[m, :] @ W_from_in[:, n] + bias[n]
//   M=65536, K=512, N=3072.  Tile 128x128, BK=16, 256 threads, 8x8/thread.
// =====================================================================
__global__ void __launch_bounds__(256) gemm_fi_kernel(
    const float* __restrict__ A,      // [MTOT, Idim]
    const float* __restrict__ W,      // [Idim, G3]
    const float* __restrict__ bias)   // [6H], uses [0:3H)
{
  __shared__ float As[16][128];       // transposed: As[k][m]
  __shared__ float Bs[16][128];       // Bs[k][n]
  const int tid = threadIdx.x;
  const int tx = tid & 15;
  const int ty = tid >> 4;
  const int bm = blockIdx.y * 128;
  const int bn = blockIdx.x * 128;

  Acc8 acc[8];
#pragma unroll
  for (int i = 0; i < 8; i++)
#pragma unroll
    for (int j = 0; j < 4; j++) acc[i].u[j] = 0ULL;

  for (int k0 = 0; k0 < Idim; k0 += 16) {
#pragma unroll
    for (int l = 0; l < 2; l++) {     // A tile: 128x16 = 512 float4
      int idx = tid + l * 256;
      int row = idx >> 2;
      int kq  = (idx & 3) << 2;
      float4 v = *(const float4*)(A + (size_t)(bm + row) * Idim + k0 + kq);
      As[kq + 0][row] = v.x; As[kq + 1][row] = v.y;
      As[kq + 2][row] = v.z; As[kq + 3][row] = v.w;
    }
#pragma unroll
    for (int l = 0; l < 2; l++) {     // W tile: 16x128 = 512 float4
      int idx = tid + l * 256;
      int row = idx >> 5;
      int nq  = (idx & 31) << 2;
      *(float4*)&Bs[row][nq] = *(const float4*)(W + (size_t)(k0 + row) * G3 + bn + nq);
    }
    __syncthreads();
#pragma unroll
    for (int k = 0; k < 16; k++) {
      V8 a, b;
      a.v[0] = *(const float4*)&As[k][ty * 8];
      a.v[1] = *(const float4*)&As[k][ty * 8 + 4];
      b.v[0] = *(const float4*)&Bs[k][tx * 8];
      b.v[1] = *(const float4*)&Bs[k][tx * 8 + 4];
#pragma unroll
      for (int i = 0; i < 8; i++) {
        unsigned long long ap = dup2(a.f[i]);
#pragma unroll
        for (int j = 0; j < 4; j++) ffma2(acc[i].u[j], ap, b.u[j]);
      }
    }
    __syncthreads();
  }

  V8 bv;
  bv.v[0] = *(const float4*)(bias + bn + tx * 8);
  bv.v[1] = *(const float4*)(bias + bn + tx * 8 + 4);
#pragma unroll
  for (int i = 0; i < 8; i++) {
#pragma unroll
    for (int j = 0; j < 8; j++) acc[i].f[j] += bv.f[j];
    float* Crow = g_fi + (size_t)(bm + ty * 8 + i) * G3 + bn + tx * 8;
    *(float4*)Crow       = acc[i].v[0];
    *(float4*)(Crow + 4) = acc[i].v[1];
  }
}

// =====================================================================
// Persistent recurrence kernel (graph node #3).
//   Grid: 128 CTAs x 256 threads. CTA c owns h columns [8c, 8c+8).
//   W slice (1024 x 24) resident in smem for the whole kernel.
//   Per step: double-buffered As tiles (128 b x 32 k, XOR-swizzled),
//   each thread: 4 batches x 1 h column x 3 gates, FFMA2 over k-pairs.
// =====================================================================
__global__ void __launch_bounds__(256, 1) recurrence_kernel(
    const float* __restrict__ Wh,     // [Hdim, G3]
    const float* __restrict__ bias,   // [6H]
    float* __restrict__ out)          // d_out: hseq [B,T,H] then h_last [B,H]
{
  extern __shared__ float smem[];
  float* Ws = smem;                         // [24][WPAD]
  float* As = smem + WS_FLOATS;             // [2][128][32], swizzled

  const int tid = threadIdx.x;
  const int tx  = tid & 7;            // h within slice
  const int ty  = tid >> 3;           // 32 groups of 4 batches
  const int c   = blockIdx.x;
  const int h   = c * 8 + tx;
  const int b0  = ty * 4;

  // ---- Load W slice into smem once: Ws[n][k], n = g*8 + j ----
  for (int f = tid; f < 6144; f += 256) {   // 1024 k * 6 float4
    int k    = f / 6;
    int rem  = f - k * 6;
    int g    = rem >> 1;
    int half = rem & 1;
    float4 v = *(const float4*)(Wh + (size_t)k * G3 + g * Hdim + c * 8 + half * 4);
    float* dst = Ws + (g * 8 + half * 4) * WPAD + k;
    dst[0 * WPAD] = v.x; dst[1 * WPAD] = v.y;
    dst[2 * WPAD] = v.z; dst[3 * WPAD] = v.w;
  }

  // bias_h for this h
  float bh[3];
#pragma unroll
  for (int g = 0; g < 3; g++) bh[g] = bias[G3 + g * Hdim + h];

  // h state resident in registers: rows b0..b0+3, column h
  float hreg[4];
#pragma unroll
  for (int i = 0; i < 4; i++) hreg[i] = 0.0f;

  __syncthreads();                    // W staged

  for (int t = 0; t < Tdim; t++) {
    // fi prefetch for this step (12 LDG, hidden under GEMM)
    float fi[4][3];
#pragma unroll
    for (int i = 0; i < 4; i++) {
      const size_t base = ((size_t)(b0 + i) * Tdim + t) * G3;
#pragma unroll
      for (int g = 0; g < 3; g++) fi[i][g] = __ldg(&g_fi[base + g * Hdim + h]);
    }

    U2 acc[4][3];
#pragma unroll
    for (int i = 0; i < 4; i++)
#pragma unroll
      for (int g = 0; g < 3; g++) acc[i][g].u = 0ULL;

    if (t > 0) {
      const float* hprev = out + (size_t)(t - 1) * Hdim;  // + b*T*H per row
      int cur = 0;

      // prologue: stage tile kb=0 into buf 0
      {
#pragma unroll
        for (int l = 0; l < 4; l++) {
          int idx = tid + l * 256;
          int b   = idx >> 3;
          int kq  = (idx & 7) << 2;
          float4 v = *(const float4*)(hprev + (size_t)b * (Tdim * Hdim) + kq);
          int sw = (((kq >> 1) ^ (((b >> 2) & 3) << 2)) << 1);
          *(float4*)(As + b * 32 + sw) = v;
        }
        __syncthreads();
      }

      for (int kb = 0; kb < Hdim; kb += 32) {
        // prefetch next tile into registers
        float4 av[4];
        if (kb + 32 < Hdim) {
#pragma unroll
          for (int l = 0; l < 4; l++) {
            int idx = tid + l * 256;
            int b   = idx >> 3;
            int kq  = (idx & 7) << 2;
            av[l] = *(const float4*)(hprev + (size_t)b * (Tdim * Hdim) + kb + 32 + kq);
          }
        }

        // compute on buf[cur]
        const float* Ab = As + cur * (Bdim * 32);
#pragma unroll
        for (int kp = 0; kp < 16; kp++) {
          unsigned long long w2[3];
#pragma unroll
          for (int g = 0; g < 3; g++)
            w2[g] = *(const unsigned long long*)(Ws + (g * 8 + tx) * WPAD + 2 * ((kb >> 1) + kp));
#pragma unroll
          for (int i = 0; i < 4; i++) {
            int row = b0 + i;
            int sw  = (kp ^ (((row >> 2) & 3) << 2)) << 1;
            unsigned long long a2 = *(const unsigned long long*)(Ab + row * 32 + sw);
            ffma2(acc[i][0].u, a2, w2[0]);
            ffma2(acc[i][1].u, a2, w2[1]);
            ffma2(acc[i][2].u, a2, w2[2]);
          }
        }

        // store prefetched tile into the other buffer
        if (kb + 32 < Hdim) {
          float* Anb = As + (cur ^ 1) * (Bdim * 32);
#pragma unroll
          for (int l = 0; l < 4; l++) {
            int idx = tid + l * 256;
            int b   = idx >> 3;
            int kq  = (idx & 7) << 2;
            int sw = (((kq >> 1) ^ (((b >> 2) & 3) << 2)) << 1);
            *(float4*)(Anb + b * 32 + sw) = av[l];
          }
        }
        __syncthreads();
        cur ^= 1;
      }
    }

    // --- gates (in-register) + write h_t ---
#pragma unroll
    for (int i = 0; i < 4; i++) {
      float hr = acc[i][0].f[0] + acc[i][0].f[1] + bh[0];
      float hz = acc[i][1].f[0] + acc[i][1].f[1] + bh[1];
      float hn = acc[i][2].f[0] + acc[i][2].f[1] + bh[2];
      float r = sigmoidf_fast(fi[i][0] + hr);
      float z = sigmoidf_fast(fi[i][1] + hz);
      float n = tanhf(fi[i][2] + r * hn);
      hreg[i] = (1.0f - z) * n + z * hreg[i];
      out[((size_t)(b0 + i) * Tdim + t) * Hdim + h] = hreg[i];
    }

    // --- grid barrier (skip after last step) ---
    if (t < Tdim - 1) {
      __syncthreads();
      if (tid == 0) {
        bar_arrive(&g_bar[t]);
        while (bar_peek(&g_bar[t]) < NCTA) { }
      }
      __syncthreads();
    }
  }

  // h_last tail of d_out
#pragma unroll
  for (int i = 0; i < 4; i++)
    out[(size_t)Bdim * Tdim * Hdim + (size_t)(b0 + i) * Hdim + h] = hreg[i];
}

// =====================================================================
extern "C" void kernel_launch(void* const* d_in, const int* in_sizes, int n_in,
                              void* d_out, int out_size) {
  (void)in_sizes; (void)n_in; (void)out_size;
  const float* inputs = (const float*)d_in[0];   // [B, T, I]
  const float* W_in   = (const float*)d_in[1];   // [I, 3H]
  const float* W_h    = (const float*)d_in[2];   // [H, 3H]
  const float* bias   = (const float*)d_in[3];   // [6H]
  float* out = (float*)d_out;

  static int smem_set = 0;
  if (!smem_set) {
    cudaFuncSetAttribute(recurrence_kernel,
                         cudaFuncAttributeMaxDynamicSharedMemorySize, SMEM_BYTES);
    smem_set = 1;
  }

  reset_kernel<<<1, Tdim>>>();

  {
    dim3 grid(G3 / 128, MTOT / 128);             // (24, 512)
    gemm_fi_kernel<<<grid, 256>>>(inputs, W_in, bias);
  }

  recurrence_kernel<<<NCTA, 256, SMEM_BYTES>>>(W_h, bias, out);
}

// round 10
// speedup vs baseline: 1.4411x; 1.0437x over previous
#include <cuda_runtime.h>
#include <cstdint>

// GRU dims
#define Bdim  128
#define Tdim  512
#define Idim  512
#define Hdim  1024
#define G3    3072          // 3*H
#define MTOT  65536         // B*T
#define NCTA  128           // persistent CTAs (<=148 SMs, all co-resident)

#define WPAD  1028          // Ws row stride (floats): 1028 % 32 == 4 -> conflict-free float4
#define WS_FLOATS (24 * WPAD)
#define AS_FLOATS (2 * Bdim * 32)
#define SMEM_BYTES ((WS_FLOATS + AS_FLOATS) * 4)

// Scratch (static __device__ — no allocations allowed)
__device__ float g_fi[(size_t)MTOT * G3];     // from_input, t-major: [T][B][3H]
__device__ unsigned g_bar[Tdim];              // one barrier slot per step

// ---------- packed fp32x2 FMA helpers ----------
__device__ __forceinline__ void ffma2(unsigned long long& d,
                                      unsigned long long a,
                                      unsigned long long b) {
  asm("fma.rn.f32x2 %0, %1, %2, %0;" : "+l"(d) : "l"(a), "l"(b));
}
__device__ __forceinline__ unsigned long long dup2(float a) {
  unsigned long long u;
  asm("mov.b64 %0, {%1, %2};" : "=l"(u) : "f"(a), "f"(a));
  return u;
}

union alignas(16) Acc8 {
  unsigned long long u[4];
  float f[8];
  float4 v[2];
};
union alignas(16) V8 {
  float4 v[2];
  unsigned long long u[4];
  float f[8];
};
union U2 { unsigned long long u; float f[2]; };
union F4 { float4 v; unsigned long long u[2]; };

__device__ __forceinline__ float sigmoidf_fast(float x) {
  return 1.0f / (1.0f + __expf(-x));
}

// release-add and acquire-load for the grid barrier
__device__ __forceinline__ void bar_arrive(unsigned* p) {
  asm volatile("red.release.gpu.global.add.u32 [%0], 1;" :: "l"(p) : "memory");
}
__device__ __forceinline__ unsigned bar_peek(const unsigned* p) {
  unsigned v;
  asm volatile("ld.acquire.gpu.global.u32 %0, [%1];" : "=r"(v) : "l"(p) : "memory");
  return v;
}

// =====================================================================
// Reset barrier slots (graph node #1)
// =====================================================================
__global__ void reset_kernel() {
  g_bar[threadIdx.x] = 0u;
}

// =====================================================================
// Phase A: g_fi[t][b][n] = inputs[b,t,:] @ W_from_in[:, n] + bias[n]
//   M=65536, K=512, N=3072.  Tile 128x128, BK=16, 256 threads, 8x8/thread.
//   Epilogue stores t-major so the recurrence reads a contiguous block per t.
// =====================================================================
__global__ void __launch_bounds__(256) gemm_fi_kernel(
    const float* __restrict__ A,      // [MTOT, Idim]  (m = b*T + t)
    const float* __restrict__ W,      // [Idim, G3]
    const float* __restrict__ bias)   // [6H], uses [0:3H)
{
  __shared__ float As[16][128];       // transposed: As[k][m]
  __shared__ float Bs[16][128];       // Bs[k][n]
  const int tid = threadIdx.x;
  const int tx = tid & 15;
  const int ty = tid >> 4;
  const int bm = blockIdx.y * 128;
  const int bn = blockIdx.x * 128;

  Acc8 acc[8];
#pragma unroll
  for (int i = 0; i < 8; i++)
#pragma unroll
    for (int j = 0; j < 4; j++) acc[i].u[j] = 0ULL;

  for (int k0 = 0; k0 < Idim; k0 += 16) {
#pragma unroll
    for (int l = 0; l < 2; l++) {     // A tile: 128x16 = 512 float4
      int idx = tid + l * 256;
      int row = idx >> 2;
      int kq  = (idx & 3) << 2;
      float4 v = *(const float4*)(A + (size_t)(bm + row) * Idim + k0 + kq);
      As[kq + 0][row] = v.x; As[kq + 1][row] = v.y;
      As[kq + 2][row] = v.z; As[kq + 3][row] = v.w;
    }
#pragma unroll
    for (int l = 0; l < 2; l++) {     // W tile: 16x128 = 512 float4
      int idx = tid + l * 256;
      int row = idx >> 5;
      int nq  = (idx & 31) << 2;
      *(float4*)&Bs[row][nq] = *(const float4*)(W + (size_t)(k0 + row) * G3 + bn + nq);
    }
    __syncthreads();
#pragma unroll
    for (int k = 0; k < 16; k++) {
      V8 a, b;
      a.v[0] = *(const float4*)&As[k][ty * 8];
      a.v[1] = *(const float4*)&As[k][ty * 8 + 4];
      b.v[0] = *(const float4*)&Bs[k][tx * 8];
      b.v[1] = *(const float4*)&Bs[k][tx * 8 + 4];
#pragma unroll
      for (int i = 0; i < 8; i++) {
        unsigned long long ap = dup2(a.f[i]);
#pragma unroll
        for (int j = 0; j < 4; j++) ffma2(acc[i].u[j], ap, b.u[j]);
      }
    }
    __syncthreads();
  }

  V8 bv;
  bv.v[0] = *(const float4*)(bias + bn + tx * 8);
  bv.v[1] = *(const float4*)(bias + bn + tx * 8 + 4);
#pragma unroll
  for (int i = 0; i < 8; i++) {
#pragma unroll
    for (int j = 0; j < 8; j++) acc[i].f[j] += bv.f[j];
    int m  = bm + ty * 8 + i;
    int b  = m >> 9;                   // m / Tdim
    int tt = m & (Tdim - 1);           // m % Tdim
    float* Crow = g_fi + ((size_t)tt * Bdim + b) * G3 + bn + tx * 8;
    *(float4*)Crow       = acc[i].v[0];
    *(float4*)(Crow + 4) = acc[i].v[1];
  }
}

// =====================================================================
// Persistent recurrence kernel (graph node #3).
//   Grid: 128 CTAs x 256 threads. CTA c owns h columns [8c, 8c+8).
//   W slice (1024 x 24) resident in smem for the whole kernel (stride WPAD).
//   Per step: double-buffered As tiles (128 b x 32 k, float4-swizzled),
//   inner loop in float4 granularity: per 2 k-pairs, 7 LDS.128 + 24 FFMA2.
// =====================================================================
__global__ void __launch_bounds__(256, 1) recurrence_kernel(
    const float* __restrict__ Wh,     // [Hdim, G3]
    const float* __restrict__ bias,   // [6H]
    float* __restrict__ out)          // d_out: hseq [B,T,H] then h_last [B,H]
{
  extern __shared__ float smem[];
  float* Ws = smem;                         // [24][WPAD]
  float* As = smem + WS_FLOATS;             // [2][128][32], float4-swizzled

  const int tid = threadIdx.x;
  const int tx  = tid & 7;            // h within slice
  const int ty  = tid >> 3;           // 32 groups of 4 batches
  const int c   = blockIdx.x;
  const int h   = c * 8 + tx;
  const int b0  = ty * 4;

  // ---- Load W slice into smem once: Ws[n][k], n = g*8 + j ----
  for (int f = tid; f < 6144; f += 256) {   // 1024 k * 6 float4
    int k    = f / 6;
    int rem  = f - k * 6;
    int g    = rem >> 1;
    int half = rem & 1;
    float4 v = *(const float4*)(Wh + (size_t)k * G3 + g * Hdim + c * 8 + half * 4);
    float* dst = Ws + (g * 8 + half * 4) * WPAD + k;
    dst[0 * WPAD] = v.x; dst[1 * WPAD] = v.y;
    dst[2 * WPAD] = v.z; dst[3 * WPAD] = v.w;
  }

  // bias_h for this h
  float bh[3];
#pragma unroll
  for (int g = 0; g < 3; g++) bh[g] = bias[G3 + g * Hdim + h];

  // h state resident in registers: rows b0..b0+3, column h
  float hreg[4];
#pragma unroll
  for (int i = 0; i < 4; i++) hreg[i] = 0.0f;

  __syncthreads();                    // W staged

  for (int t = 0; t < Tdim; t++) {
    // fi prefetch for this step (12 LDG from the contiguous step-t block)
    float fi[4][3];
#pragma unroll
    for (int i = 0; i < 4; i++) {
      const size_t base = ((size_t)t * Bdim + (b0 + i)) * G3;
#pragma unroll
      for (int g = 0; g < 3; g++) fi[i][g] = __ldg(&g_fi[base + g * Hdim + h]);
    }

    U2 acc[4][3];
#pragma unroll
    for (int i = 0; i < 4; i++)
#pragma unroll
      for (int g = 0; g < 3; g++) acc[i][g].u = 0ULL;

    if (t > 0) {
      const float* hprev = out + (size_t)(t - 1) * Hdim;  // + b*T*H per row
      int cur = 0;

      // prologue: stage tile kb=0 into buf 0
      {
#pragma unroll
        for (int l = 0; l < 4; l++) {
          int idx = tid + l * 256;
          int b   = idx >> 3;
          int gq  = idx & 7;                 // float4 group within row
          float4 v = *(const float4*)(hprev + (size_t)b * (Tdim * Hdim) + gq * 4);
          int sw = (gq ^ ((b >> 2) & 7)) << 2;
          *(float4*)(As + b * 32 + sw) = v;
        }
        __syncthreads();
      }

      for (int kb = 0; kb < Hdim; kb += 32) {
        // prefetch next tile into registers
        float4 av[4];
        if (kb + 32 < Hdim) {
#pragma unroll
          for (int l = 0; l < 4; l++) {
            int idx = tid + l * 256;
            int b   = idx >> 3;
            int gq  = idx & 7;
            av[l] = *(const float4*)(hprev + (size_t)b * (Tdim * Hdim) + kb + 32 + gq * 4);
          }
        }

        // compute on buf[cur]: 8 float4-groups (kp2), each = 2 k-pairs
        const float* Ab = As + cur * (Bdim * 32);
#pragma unroll
        for (int kp2 = 0; kp2 < 8; kp2++) {
          F4 w4[3];
#pragma unroll
          for (int g = 0; g < 3; g++)
            w4[g].v = *(const float4*)(Ws + (g * 8 + tx) * WPAD + kb + kp2 * 4);
#pragma unroll
          for (int i = 0; i < 4; i++) {
            int row = b0 + i;
            F4 a4;
            a4.v = *(const float4*)(Ab + row * 32 + ((kp2 ^ ((row >> 2) & 7)) << 2));
            ffma2(acc[i][0].u, a4.u[0], w4[0].u[0]);
            ffma2(acc[i][1].u, a4.u[0], w4[1].u[0]);
            ffma2(acc[i][2].u, a4.u[0], w4[2].u[0]);
            ffma2(acc[i][0].u, a4.u[1], w4[0].u[1]);
            ffma2(acc[i][1].u, a4.u[1], w4[1].u[1]);
            ffma2(acc[i][2].u, a4.u[1], w4[2].u[1]);
          }
        }

        // store prefetched tile into the other buffer
        if (kb + 32 < Hdim) {
          float* Anb = As + (cur ^ 1) * (Bdim * 32);
#pragma unroll
          for (int l = 0; l < 4; l++) {
            int idx = tid + l * 256;
            int b   = idx >> 3;
            int gq  = idx & 7;
            int sw  = (gq ^ ((b >> 2) & 7)) << 2;
            *(float4*)(Anb + b * 32 + sw) = av[l];
          }
        }
        __syncthreads();
        cur ^= 1;
      }
    }

    // --- gates (in-register) + write h_t ---
#pragma unroll
    for (int i = 0; i < 4; i++) {
      float hr = acc[i][0].f[0] + acc[i][0].f[1] + bh[0];
      float hz = acc[i][1].f[0] + acc[i][1].f[1] + bh[1];
      float hn = acc[i][2].f[0] + acc[i][2].f[1] + bh[2];
      float r = sigmoidf_fast(fi[i][0] + hr);
      float z = sigmoidf_fast(fi[i][1] + hz);
      float n = tanhf(fi[i][2] + r * hn);
      hreg[i] = (1.0f - z) * n + z * hreg[i];
      out[((size_t)(b0 + i) * Tdim + t) * Hdim + h] = hreg[i];
    }

    // --- grid barrier (skip after last step) ---
    if (t < Tdim - 1) {
      __syncthreads();
      if (tid == 0) {
        bar_arrive(&g_bar[t]);
        while (bar_peek(&g_bar[t]) < NCTA) { __nanosleep(32); }
      }
      __syncthreads();
    }
  }

  // h_last tail of d_out
#pragma unroll
  for (int i = 0; i < 4; i++)
    out[(size_t)Bdim * Tdim * Hdim + (size_t)(b0 + i) * Hdim + h] = hreg[i];
}

// =====================================================================
extern "C" void kernel_launch(void* const* d_in, const int* in_sizes, int n_in,
                              void* d_out, int out_size) {
  (void)in_sizes; (void)n_in; (void)out_size;
  const float* inputs = (const float*)d_in[0];   // [B, T, I]
  const float* W_in   = (const float*)d_in[1];   // [I, 3H]
  const float* W_h    = (const float*)d_in[2];   // [H, 3H]
  const float* bias   = (const float*)d_in[3];   // [6H]
  float* out = (float*)d_out;

  static int smem_set = 0;
  if (!smem_set) {
    cudaFuncSetAttribute(recurrence_kernel,
                         cudaFuncAttributeMaxDynamicSharedMemorySize, SMEM_BYTES);
    smem_set = 1;
  }

  reset_kernel<<<1, Tdim>>>();

  {
    dim3 grid(G3 / 128, MTOT / 128);             // (24, 512)
    gemm_fi_kernel<<<grid, 256>>>(inputs, W_in, bias);
  }

  recurrence_kernel<<<NCTA, 256, SMEM_BYTES>>>(W_h, bias, out);
}

// round 12
// speedup vs baseline: 2.4067x; 1.6700x over previous
#include <cuda_runtime.h>
#include <cuda_bf16.h>
#include <cstdint>

// GRU dims
#define Bdim  128
#define Tdim  512
#define Idim  512
#define Hdim  1024
#define G3    3072
#define MTOT  65536
#define NCTA  128

// ---- recurrence smem layout (bytes) ----
#define OFF_BHI   0
#define OFF_BLO   49152
#define OFF_A     98304
#define A_HI(buf) (OFF_A + (buf) * 32768)
#define A_LO(buf) (A_HI(buf) + 16384)
#define SMEM_REC  (OFF_A + 65536)           // 163840

// Scratch (static __device__ — no allocations allowed)
__device__ float g_fi[(size_t)MTOT * G3];               // [T][B][3H]
__device__ __nv_bfloat16 g_hh[(size_t)Bdim * Hdim];     // h hi
__device__ __nv_bfloat16 g_hl[(size_t)Bdim * Hdim];     // h lo
__device__ unsigned g_bar[Tdim];

// ---------- packed fp32x2 FMA helpers (phase A) ----------
__device__ __forceinline__ void ffma2(unsigned long long& d,
                                      unsigned long long a,
                                      unsigned long long b) {
  asm("fma.rn.f32x2 %0, %1, %2, %0;" : "+l"(d) : "l"(a), "l"(b));
}
__device__ __forceinline__ unsigned long long dup2(float a) {
  unsigned long long u;
  asm("mov.b64 %0, {%1, %2};" : "=l"(u) : "f"(a), "f"(a));
  return u;
}
union alignas(16) Acc8 { unsigned long long u[4]; float f[8]; float4 v[2]; };
union alignas(16) V8   { float4 v[2]; unsigned long long u[4]; float f[8]; };

__device__ __forceinline__ float sigmoidf_fast(float x) {
  return 1.0f / (1.0f + __expf(-x));
}

// ---------- grid barrier ----------
__device__ __forceinline__ void bar_arrive(unsigned* p) {
  asm volatile("red.release.gpu.global.add.u32 [%0], 1;" :: "l"(p) : "memory");
}
__device__ __forceinline__ unsigned bar_peek(const unsigned* p) {
  unsigned v;
  asm volatile("ld.acquire.gpu.global.u32 %0, [%1];" : "=r"(v) : "l"(p) : "memory");
  return v;
}

// ---------- HMMA / ldmatrix ----------
__device__ __forceinline__ uint32_t smem_u32(const void* p) {
  uint32_t a;
  asm("{ .reg .u64 t; cvta.to.shared.u64 t, %1; cvt.u32.u64 %0, t; }" : "=r"(a) : "l"(p));
  return a;
}
#define LDSM_X4(r, a) \
  asm volatile("ldmatrix.sync.aligned.m8n8.x4.shared.b16 {%0,%1,%2,%3}, [%4];" \
    : "=r"((r)[0]), "=r"((r)[1]), "=r"((r)[2]), "=r"((r)[3]) : "r"(a))
#define LDSM_X2(r, a) \
  asm volatile("ldmatrix.sync.aligned.m8n8.x2.shared.b16 {%0,%1}, [%2];" \
    : "=r"((r)[0]), "=r"((r)[1]) : "r"(a))

__device__ __forceinline__ void mma16816(float* d, const uint32_t* a,
                                         uint32_t b0, uint32_t b1) {
  asm volatile(
    "mma.sync.aligned.m16n8k16.row.col.f32.bf16.bf16.f32 "
    "{%0,%1,%2,%3}, {%4,%5,%6,%7}, {%8,%9}, {%0,%1,%2,%3};"
    : "+f"(d[0]), "+f"(d[1]), "+f"(d[2]), "+f"(d[3])
    : "r"(a[0]), "r"(a[1]), "r"(a[2]), "r"(a[3]), "r"(b0), "r"(b1));
}

// =====================================================================
__global__ void reset_kernel() { g_bar[threadIdx.x] = 0u; }

// =====================================================================
// Phase A (scalar FFMA2 GEMM): g_fi[t][b][n] = inputs@W_in + bias_in
// =====================================================================
__global__ void __launch_bounds__(256) gemm_fi_kernel(
    const float* __restrict__ A, const float* __restrict__ W,
    const float* __restrict__ bias)
{
  __shared__ float As[16][128];
  __shared__ float Bs[16][128];
  const int tid = threadIdx.x;
  const int tx = tid & 15;
  const int ty = tid >> 4;
  const int bm = blockIdx.y * 128;
  const int bn = blockIdx.x * 128;

  Acc8 acc[8];
#pragma unroll
  for (int i = 0; i < 8; i++)
#pragma unroll
    for (int j = 0; j < 4; j++) acc[i].u[j] = 0ULL;

  for (int k0 = 0; k0 < Idim; k0 += 16) {
#pragma unroll
    for (int l = 0; l < 2; l++) {
      int idx = tid + l * 256;
      int row = idx >> 2;
      int kq  = (idx & 3) << 2;
      float4 v = *(const float4*)(A + (size_t)(bm + row) * Idim + k0 + kq);
      As[kq + 0][row] = v.x; As[kq + 1][row] = v.y;
      As[kq + 2][row] = v.z; As[kq + 3][row] = v.w;
    }
#pragma unroll
    for (int l = 0; l < 2; l++) {
      int idx = tid + l * 256;
      int row = idx >> 5;
      int nq  = (idx & 31) << 2;
      *(float4*)&Bs[row][nq] = *(const float4*)(W + (size_t)(k0 + row) * G3 + bn + nq);
    }
    __syncthreads();
#pragma unroll
    for (int k = 0; k < 16; k++) {
      V8 a, b;
      a.v[0] = *(const float4*)&As[k][ty * 8];
      a.v[1] = *(const float4*)&As[k][ty * 8 + 4];
      b.v[0] = *(const float4*)&Bs[k][tx * 8];
      b.v[1] = *(const float4*)&Bs[k][tx * 8 + 4];
#pragma unroll
      for (int i = 0; i < 8; i++) {
        unsigned long long ap = dup2(a.f[i]);
#pragma unroll
        for (int j = 0; j < 4; j++) ffma2(acc[i].u[j], ap, b.u[j]);
      }
    }
    __syncthreads();
  }

  V8 bv;
  bv.v[0] = *(const float4*)(bias + bn + tx * 8);
  bv.v[1] = *(const float4*)(bias + bn + tx * 8 + 4);
#pragma unroll
  for (int i = 0; i < 8; i++) {
#pragma unroll
    for (int j = 0; j < 8; j++) acc[i].f[j] += bv.f[j];
    int m  = bm + ty * 8 + i;
    int b  = m >> 9;
    int tt = m & (Tdim - 1);
    float* Crow = g_fi + ((size_t)tt * Bdim + b) * G3 + bn + tx * 8;
    *(float4*)Crow       = acc[i].v[0];
    *(float4*)(Crow + 4) = acc[i].v[1];
  }
}

// =====================================================================
// Persistent HMMA recurrence: 128 CTAs x 256 threads (8 warps).
// CTA c owns h-cols [8c, 8c+8): D[128 b x 24 n] = h_prev @ Wslice,
// split-bf16 3 passes via mma.sync.m16n8k16. Warp w = m-tile rows [16w,16w+16).
// W (24 x 1024 hi/lo) in smem whole kernel; h staged per step as 16
// double-buffered 128x64 bf16 tiles (swizzled for ldmatrix).
// =====================================================================
__global__ void __launch_bounds__(256, 1) recurrence_kernel(
    const float* __restrict__ Wh,     // [Hdim, G3]
    const float* __restrict__ bias,   // [6H]
    float* __restrict__ out)          // hseq [B,T,H] then h_last [B,H]
{
  extern __shared__ __align__(1024) char smem[];
  const uint32_t sb = smem_u32(smem);
  const int tid = threadIdx.x;
  const int w   = tid >> 5;           // warp 0..7 = m-tile
  const int l   = tid & 31;           // lane
  const int c   = blockIdx.x;
  const int cb  = c * 8;              // global h col base

  // ---- Stage W slice (transposed, split hi/lo) into smem once ----
  // Atom layout: atom = (k>>6)*3 + (n>>3); within: row=n&7, 64 k bf16 per row,
  // 16B-unit swizzle: byteoff = atom*1024 + row*128 + (((k&63)*2) ^ (row<<4))
  for (int idx = tid; idx < 24 * 1024; idx += 256) {
    int n = idx >> 10;
    int k = idx & 1023;
    float wv = Wh[(size_t)k * G3 + (n >> 3) * Hdim + cb + (n & 7)];
    __nv_bfloat16 hi = __float2bfloat16_rn(wv);
    __nv_bfloat16 lo = __float2bfloat16_rn(wv - __bfloat162float(hi));
    int row = n & 7;
    uint32_t off = (uint32_t)(((k >> 6) * 3 + (n >> 3)) * 1024 + row * 128 +
                              ((((k & 63) * 2)) ^ (row << 4)));
    *(__nv_bfloat16*)(smem + OFF_BHI + off) = hi;
    *(__nv_bfloat16*)(smem + OFF_BLO + off) = lo;
  }
  __syncthreads();

  // ---- per-lane ldmatrix address components ----
  // A (m16x k16 tile, x4): lanes 0-7 rows R..R+7 k0 | 8-15 rows R+8.. k0 |
  //                        16-23 rows R..R+7 k8 | 24-31 rows R+8.. k8
  const int arow = w * 16 + (l & 7) + ((l >> 3) & 1) * 8;
  const uint32_t QA = ((uint32_t)((l >> 4) & 1) * 16) ^ (((uint32_t)arow & 7) << 4);
  const uint32_t PAr = (uint32_t)arow * 128;
  // B x4 (ntiles 0,1): lanes 0-7 nt0 k0 | 8-15 nt0 k8 | 16-23 nt1 k0 | 24-31 nt1 k8
  const int brow = l & 7;
  const int bnt  = (l >> 4) & 1;
  const uint32_t QB = ((uint32_t)((l >> 3) & 1) * 16) ^ ((uint32_t)brow << 4);
  const uint32_t PBr = (uint32_t)bnt * 1024 + (uint32_t)brow * 128;

  // ---- epilogue ownership: lane handles batches (16w+quad, +8), cols c0,c0+1
  const int quad = l >> 2;
  const int c0   = (l & 3) * 2;
  const int bA   = w * 16 + quad;
  const int bB   = bA + 8;

  float bh[3][2];
#pragma unroll
  for (int g = 0; g < 3; g++) {
    bh[g][0] = bias[G3 + g * Hdim + cb + c0];
    bh[g][1] = bias[G3 + g * Hdim + cb + c0 + 1];
  }

  float hreg[2][2] = {{0.f, 0.f}, {0.f, 0.f}};

  for (int t = 0; t < Tdim; t++) {
    // fi for this lane's 2 batches x 3 gates x 2 cols
    float2 fi[2][3];
#pragma unroll
    for (int bi = 0; bi < 2; bi++) {
      const int b = bi ? bB : bA;
      const float* fb = g_fi + ((size_t)t * Bdim + b) * G3 + cb + c0;
#pragma unroll
      for (int g = 0; g < 3; g++)
        fi[bi][g] = __ldg((const float2*)(fb + g * Hdim));
    }

    float d[3][4];
#pragma unroll
    for (int g = 0; g < 3; g++)
#pragma unroll
      for (int j = 0; j < 4; j++) d[g][j] = 0.0f;

    if (t > 0) {
      // ---- prologue: LDG+STS tile 0, sync, LDG tile 1 ----
      uint4 ph[4], pl[4];
#pragma unroll
      for (int q4 = 0; q4 < 4; q4++) {
        int idx = tid + q4 * 256;
        int b = idx >> 3, q = idx & 7;
        ph[q4] = *(const uint4*)(g_hh + (size_t)b * Hdim + q * 8);
        pl[q4] = *(const uint4*)(g_hl + (size_t)b * Hdim + q * 8);
      }
#pragma unroll
      for (int q4 = 0; q4 < 4; q4++) {
        int idx = tid + q4 * 256;
        int b = idx >> 3, q = idx & 7;
        uint32_t so = (uint32_t)b * 128 + (((uint32_t)q * 16) ^ (((uint32_t)b & 7) << 4));
        *(uint4*)(smem + A_HI(0) + so) = ph[q4];
        *(uint4*)(smem + A_LO(0) + so) = pl[q4];
      }
      __syncthreads();
#pragma unroll
      for (int q4 = 0; q4 < 4; q4++) {
        int idx = tid + q4 * 256;
        int b = idx >> 3, q = idx & 7;
        ph[q4] = *(const uint4*)(g_hh + (size_t)b * Hdim + 64 + q * 8);
        pl[q4] = *(const uint4*)(g_hl + (size_t)b * Hdim + 64 + q * 8);
      }

      for (int i = 0; i < 16; i++) {
        const int buf = i & 1;
        const uint32_t pa_hi = sb + A_HI(buf) + PAr;
        const uint32_t pa_lo = sb + A_LO(buf) + PAr;
        const uint32_t pb_hi = sb + OFF_BHI + (uint32_t)i * 3072 + PBr;
        const uint32_t pb_lo = sb + OFF_BLO + (uint32_t)i * 3072 + PBr;
        const uint32_t pb2_hi = sb + OFF_BHI + (uint32_t)i * 3072 + 2048 + (uint32_t)brow * 128;
        const uint32_t pb2_lo = sb + OFF_BLO + (uint32_t)i * 3072 + 2048 + (uint32_t)brow * 128;

#pragma unroll
        for (int kk = 0; kk < 4; kk++) {
          const uint32_t ao = ((uint32_t)kk * 32) ^ QA;
          const uint32_t bo = ((uint32_t)kk * 32) ^ QB;
          uint32_t Ah[4], Al[4], Bh[4], Bl[4], B2h[2], B2l[2];
          LDSM_X4(Ah, pa_hi + ao);
          LDSM_X4(Al, pa_lo + ao);
          LDSM_X4(Bh, pb_hi + bo);
          LDSM_X4(Bl, pb_lo + bo);
          LDSM_X2(B2h, pb2_hi + bo);
          LDSM_X2(B2l, pb2_lo + bo);
          // 3 split passes x 3 n-tiles
          mma16816(d[0], Ah, Bh[0], Bh[1]);
          mma16816(d[0], Ah, Bl[0], Bl[1]);
          mma16816(d[0], Al, Bh[0], Bh[1]);
          mma16816(d[1], Ah, Bh[2], Bh[3]);
          mma16816(d[1], Ah, Bl[2], Bl[3]);
          mma16816(d[1], Al, Bh[2], Bh[3]);
          mma16816(d[2], Ah, B2h[0], B2h[1]);
          mma16816(d[2], Ah, B2l[0], B2l[1]);
          mma16816(d[2], Al, B2h[0], B2h[1]);
        }

        if (i < 15) {
          // store prefetched tile i+1 into other buffer
#pragma unroll
          for (int q4 = 0; q4 < 4; q4++) {
            int idx = tid + q4 * 256;
            int b = idx >> 3, q = idx & 7;
            uint32_t so = (uint32_t)b * 128 + (((uint32_t)q * 16) ^ (((uint32_t)b & 7) << 4));
            *(uint4*)(smem + A_HI(buf ^ 1) + so) = ph[q4];
            *(uint4*)(smem + A_LO(buf ^ 1) + so) = pl[q4];
          }
          if (i < 14) {
            const int kb = (i + 2) * 64;
#pragma unroll
            for (int q4 = 0; q4 < 4; q4++) {
              int idx = tid + q4 * 256;
              int b = idx >> 3, q = idx & 7;
              ph[q4] = *(const uint4*)(g_hh + (size_t)b * Hdim + kb + q * 8);
              pl[q4] = *(const uint4*)(g_hl + (size_t)b * Hdim + kb + q * 8);
            }
          }
        }
        __syncthreads();
      }
    }

    // ---- gates + writes for 2 batches x 2 cols ----
#pragma unroll
    for (int bi = 0; bi < 2; bi++) {
      const int b = bi ? bB : bA;
      float hv[2];
#pragma unroll
      for (int j = 0; j < 2; j++) {
        float fr = (j ? fi[bi][0].y : fi[bi][0].x);
        float fz = (j ? fi[bi][1].y : fi[bi][1].x);
        float fn = (j ? fi[bi][2].y : fi[bi][2].x);
        float rr = sigmoidf_fast(fr + d[0][bi * 2 + j] + bh[0][j]);
        float zz = sigmoidf_fast(fz + d[1][bi * 2 + j] + bh[1][j]);
        float nn = tanhf(fn + rr * (d[2][bi * 2 + j] + bh[2][j]));
        hv[j] = (1.0f - zz) * nn + zz * hreg[bi][j];
        hreg[bi][j] = hv[j];
      }
      // hseq
      *(float2*)(out + ((size_t)b * Tdim + t) * Hdim + cb + c0) = make_float2(hv[0], hv[1]);
      // bf16 hi/lo state
      __nv_bfloat162 h2 = __floats2bfloat162_rn(hv[0], hv[1]);
      float l0 = hv[0] - __bfloat162float(__float2bfloat16_rn(hv[0]));
      float l1 = hv[1] - __bfloat162float(__float2bfloat16_rn(hv[1]));
      __nv_bfloat162 l2 = __floats2bfloat162_rn(l0, l1);
      *(__nv_bfloat162*)(g_hh + (size_t)b * Hdim + cb + c0) = h2;
      *(__nv_bfloat162*)(g_hl + (size_t)b * Hdim + cb + c0) = l2;
      if (t == Tdim - 1) {
        *(float2*)(out + (size_t)Bdim * Tdim * Hdim + (size_t)b * Hdim + cb + c0) =
            make_float2(hv[0], hv[1]);
      }
    }

    // ---- grid barrier ----
    if (t < Tdim - 1) {
      __syncthreads();
      if (tid == 0) {
        bar_arrive(&g_bar[t]);
        while (bar_peek(&g_bar[t]) < NCTA) { __nanosleep(32); }
      }
      __syncthreads();
    }
  }
}

// =====================================================================
extern "C" void kernel_launch(void* const* d_in, const int* in_sizes, int n_in,
                              void* d_out, int out_size) {
  (void)in_sizes; (void)n_in; (void)out_size;
  const float* inputs = (const float*)d_in[0];
  const float* W_in   = (const float*)d_in[1];
  const float* W_h    = (const float*)d_in[2];
  const float* bias   = (const float*)d_in[3];
  float* out = (float*)d_out;

  static int smem_set = 0;
  if (!smem_set) {
    cudaFuncSetAttribute(recurrence_kernel,
                         cudaFuncAttributeMaxDynamicSharedMemorySize, SMEM_REC);
    smem_set = 1;
  }

  reset_kernel<<<1, Tdim>>>();

  {
    dim3 grid(G3 / 128, MTOT / 128);
    gemm_fi_kernel<<<grid, 256>>>(inputs, W_in, bias);
  }

  recurrence_kernel<<<NCTA, 256, SMEM_REC>>>(W_h, bias, out);
}

// round 13
// speedup vs baseline: 3.1111x; 1.2927x over previous
#include <cuda_runtime.h>
#include <cuda_bf16.h>
#include <cstdint>

// GRU dims
#define Bdim  128
#define Tdim  512
#define Idim  512
#define Hdim  1024
#define G3    3072
#define MTOT  65536
#define NCTA  128

// ---- recurrence smem layout (bytes) ----
#define OFF_BHI   0
#define OFF_BLO   49152
#define OFF_A     98304
#define A_HI(buf) (OFF_A + (buf) * 32768)
#define A_LO(buf) (A_HI(buf) + 16384)
#define SMEM_REC  (OFF_A + 65536)           // 163840

// ---- phase A smem layout ----
#define PA_AH(buf) ((buf) * 65536 + 0)
#define PA_AL(buf) ((buf) * 65536 + 16384)
#define PA_BH(buf) ((buf) * 65536 + 32768)
#define PA_BL(buf) ((buf) * 65536 + 49152)
#define PA_SMEM    131072

// Scratch (static __device__ — no allocations allowed)
__device__ float g_fi[(size_t)MTOT * G3];               // [T][B][3H]
__device__ __nv_bfloat16 g_ah[(size_t)MTOT * Idim];     // inputs hi
__device__ __nv_bfloat16 g_al[(size_t)MTOT * Idim];     // inputs lo
__device__ __nv_bfloat16 g_wh[(size_t)G3 * Idim];       // W_in^T hi  [n][k]
__device__ __nv_bfloat16 g_wl[(size_t)G3 * Idim];       // W_in^T lo
__device__ __nv_bfloat16 g_hh[(size_t)Bdim * Hdim];     // h hi
__device__ __nv_bfloat16 g_hl[(size_t)Bdim * Hdim];     // h lo
__device__ unsigned g_bar[Tdim];

__device__ __forceinline__ float sigmoidf_fast(float x) {
  return 1.0f / (1.0f + __expf(-x));
}

// ---------- grid barrier ----------
__device__ __forceinline__ void bar_arrive(unsigned* p) {
  asm volatile("red.release.gpu.global.add.u32 [%0], 1;" :: "l"(p) : "memory");
}
__device__ __forceinline__ unsigned bar_peek(const unsigned* p) {
  unsigned v;
  asm volatile("ld.acquire.gpu.global.u32 %0, [%1];" : "=r"(v) : "l"(p) : "memory");
  return v;
}

// ---------- HMMA / ldmatrix / cp.async ----------
__device__ __forceinline__ uint32_t smem_u32(const void* p) {
  uint32_t a;
  asm("{ .reg .u64 t; cvta.to.shared.u64 t, %1; cvt.u32.u64 %0, t; }" : "=r"(a) : "l"(p));
  return a;
}
#define LDSM_X4(r, a) \
  asm volatile("ldmatrix.sync.aligned.m8n8.x4.shared.b16 {%0,%1,%2,%3}, [%4];" \
    : "=r"((r)[0]), "=r"((r)[1]), "=r"((r)[2]), "=r"((r)[3]) : "r"(a))
#define LDSM_X2(r, a) \
  asm volatile("ldmatrix.sync.aligned.m8n8.x2.shared.b16 {%0,%1}, [%2];" \
    : "=r"((r)[0]), "=r"((r)[1]) : "r"(a))

__device__ __forceinline__ void mma16816(float* d, const uint32_t* a,
                                         uint32_t b0, uint32_t b1) {
  asm volatile(
    "mma.sync.aligned.m16n8k16.row.col.f32.bf16.bf16.f32 "
    "{%0,%1,%2,%3}, {%4,%5,%6,%7}, {%8,%9}, {%0,%1,%2,%3};"
    : "+f"(d[0]), "+f"(d[1]), "+f"(d[2]), "+f"(d[3])
    : "r"(a[0]), "r"(a[1]), "r"(a[2]), "r"(a[3]), "r"(b0), "r"(b1));
}

__device__ __forceinline__ void cp16(uint32_t dst, const void* src) {
  asm volatile("cp.async.cg.shared.global [%0], [%1], 16;" :: "r"(dst), "l"(src));
}
#define CP_COMMIT() asm volatile("cp.async.commit_group;" ::: "memory")
#define CP_WAIT0()  asm volatile("cp.async.wait_group 0;" ::: "memory")

// =====================================================================
__global__ void reset_kernel() { g_bar[threadIdx.x] = 0u; }

// =====================================================================
// Convert inputs -> bf16 hi/lo  (33.5M elems, 2 per thread)
// =====================================================================
__global__ void __launch_bounds__(256) conv_in_kernel(const float* __restrict__ x) {
  size_t i = ((size_t)blockIdx.x * 256 + threadIdx.x) * 2;
  float2 v = *(const float2*)(x + i);
  __nv_bfloat16 h0 = __float2bfloat16_rn(v.x);
  __nv_bfloat16 h1 = __float2bfloat16_rn(v.y);
  __nv_bfloat16 l0 = __float2bfloat16_rn(v.x - __bfloat162float(h0));
  __nv_bfloat16 l1 = __float2bfloat16_rn(v.y - __bfloat162float(h1));
  *(__nv_bfloat162*)(g_ah + i) = __nv_bfloat162(h0, h1);
  *(__nv_bfloat162*)(g_al + i) = __nv_bfloat162(l0, l1);
}

// =====================================================================
// Convert + transpose W_in [K=512][N=3072] -> g_wh/g_wl [N][K] hi/lo
// =====================================================================
__global__ void __launch_bounds__(256) conv_w_kernel(const float* __restrict__ W) {
  __shared__ float tile[32][33];
  const int tx = threadIdx.x & 31;
  const int ty = threadIdx.x >> 5;        // 0..7
  const int kb = blockIdx.y * 32;         // k block
  const int nb = blockIdx.x * 32;         // n block
#pragma unroll
  for (int i = 0; i < 4; i++)
    tile[ty + i * 8][tx] = W[(size_t)(kb + ty + i * 8) * G3 + nb + tx];
  __syncthreads();
#pragma unroll
  for (int i = 0; i < 4; i++) {
    int n = nb + ty + i * 8;
    int k = kb + tx;
    float v = tile[tx][ty + i * 8];
    __nv_bfloat16 h = __float2bfloat16_rn(v);
    g_wh[(size_t)n * Idim + k] = h;
    g_wl[(size_t)n * Idim + k] = __float2bfloat16_rn(v - __bfloat162float(h));
  }
}

// =====================================================================
// Phase A (HMMA): g_fi[t][b][n] = inputs@W_in + bias_in, split-bf16 3-pass.
// Tile 128(M) x 128(N), BK=64, 256 thr, warp grid 2x4 (warp = 64m x 32n).
// cp.async double-buffered. grid = (24, 512).
// =====================================================================
__global__ void __launch_bounds__(256) gemm_fi_mma_kernel(
    const float* __restrict__ bias)
{
  extern __shared__ __align__(1024) char smem[];
  const uint32_t sb = smem_u32(smem);
  const int tid = threadIdx.x;
  const int w   = tid >> 5;
  const int l   = tid & 31;
  const int mw  = w & 1;                  // m64 half
  const int nw  = w >> 1;                 // n32 quarter
  const int bm  = blockIdx.y * 128;
  const int bn  = blockIdx.x * 128;

  // staging: idx = tid + q4*256 -> row (0..127), q (16B unit 0..7)
  // dst off = row*128 + ((q*16) ^ ((row&7)<<4))
  const int srow = tid >> 3;
  const int sq   = tid & 7;
  const uint32_t soff0 = (uint32_t)srow * 128 + (((uint32_t)sq * 16) ^ (((uint32_t)srow & 7) << 4));

  float acc[4][4][4];
#pragma unroll
  for (int mt = 0; mt < 4; mt++)
#pragma unroll
    for (int nt = 0; nt < 4; nt++)
#pragma unroll
      for (int j = 0; j < 4; j++) acc[mt][nt][j] = 0.0f;

  // ldmatrix per-lane components (row&7 == l&7 for all tiles)
  const uint32_t PAr = (uint32_t)(((l & 7) + ((l >> 3) & 1) * 8)) * 128;
  const uint32_t QA  = ((uint32_t)((l >> 4) & 1) * 16) ^ (((uint32_t)l & 7) << 4);
  const uint32_t PBr = (uint32_t)(((l & 7) + ((l >> 4) & 1) * 8)) * 128;
  const uint32_t QB  = ((uint32_t)((l >> 3) & 1) * 16) ^ (((uint32_t)l & 7) << 4);

  auto stage = [&](int buf, int kb) {
#pragma unroll
    for (int q4 = 0; q4 < 4; q4++) {
      int row = srow + q4 * 32;
      uint32_t so = soff0 + (uint32_t)q4 * 32 * 128;
      const size_t asrc = (size_t)(bm + row) * Idim + kb + sq * 8;
      const size_t bsrc = (size_t)(bn + row) * Idim + kb + sq * 8;
      cp16(sb + PA_AH(buf) + so, g_ah + asrc);
      cp16(sb + PA_AL(buf) + so, g_al + asrc);
      cp16(sb + PA_BH(buf) + so, g_wh + bsrc);
      cp16(sb + PA_BL(buf) + so, g_wl + bsrc);
    }
  };

  stage(0, 0);
  CP_COMMIT();
  CP_WAIT0();
  __syncthreads();

  for (int kt = 0; kt < 8; kt++) {
    const int buf = kt & 1;
    if (kt < 7) { stage(buf ^ 1, (kt + 1) * 64); CP_COMMIT(); }

    const uint32_t ah_b = sb + PA_AH(buf) + (uint32_t)(mw * 64) * 128 + PAr;
    const uint32_t al_b = sb + PA_AL(buf) + (uint32_t)(mw * 64) * 128 + PAr;
    const uint32_t bh_b = sb + PA_BH(buf) + (uint32_t)(nw * 32) * 128 + PBr;
    const uint32_t bl_b = sb + PA_BL(buf) + (uint32_t)(nw * 32) * 128 + PBr;

#pragma unroll
    for (int kk = 0; kk < 4; kk++) {
      const uint32_t ao = ((uint32_t)kk * 32) ^ QA;
      const uint32_t bo = ((uint32_t)kk * 32) ^ QB;
      uint32_t Ah[4][4], Al[4][4];
#pragma unroll
      for (int mt = 0; mt < 4; mt++) {
        LDSM_X4(Ah[mt], ah_b + (uint32_t)(mt * 16) * 128 + ao);
        LDSM_X4(Al[mt], al_b + (uint32_t)(mt * 16) * 128 + ao);
      }
#pragma unroll
      for (int ntp = 0; ntp < 2; ntp++) {
        uint32_t Bh[4], Bl[4];
        LDSM_X4(Bh, bh_b + (uint32_t)(ntp * 16) * 128 + bo);
        LDSM_X4(Bl, bl_b + (uint32_t)(ntp * 16) * 128 + bo);
#pragma unroll
        for (int mt = 0; mt < 4; mt++) {
          mma16816(acc[mt][ntp * 2],     Ah[mt], Bh[0], Bh[1]);
          mma16816(acc[mt][ntp * 2],     Ah[mt], Bl[0], Bl[1]);
          mma16816(acc[mt][ntp * 2],     Al[mt], Bh[0], Bh[1]);
          mma16816(acc[mt][ntp * 2 + 1], Ah[mt], Bh[2], Bh[3]);
          mma16816(acc[mt][ntp * 2 + 1], Ah[mt], Bl[2], Bl[3]);
          mma16816(acc[mt][ntp * 2 + 1], Al[mt], Bh[2], Bh[3]);
        }
      }
    }

    if (kt < 7) CP_WAIT0();
    __syncthreads();
  }

  // ---- epilogue: acc + bias -> g_fi [t][b][n] ----
  const int quad = l >> 2;
  const int cq   = (l & 3) * 2;
#pragma unroll
  for (int nt = 0; nt < 4; nt++) {
    const int col = bn + nw * 32 + nt * 8 + cq;
    const float2 bv = *(const float2*)(bias + col);
#pragma unroll
    for (int mt = 0; mt < 4; mt++) {
      int m0 = bm + mw * 64 + mt * 16 + quad;
#pragma unroll
      for (int half = 0; half < 2; half++) {
        int m  = m0 + half * 8;
        int b  = m >> 9;
        int tt = m & (Tdim - 1);
        *(float2*)(g_fi + ((size_t)tt * Bdim + b) * G3 + col) =
            make_float2(acc[mt][nt][half * 2] + bv.x, acc[mt][nt][half * 2 + 1] + bv.y);
      }
    }
  }
}

// =====================================================================
// Persistent HMMA recurrence (unchanged from R12): 128 CTAs x 256 threads.
// =====================================================================
__global__ void __launch_bounds__(256, 1) recurrence_kernel(
    const float* __restrict__ Wh,     // [Hdim, G3]
    const float* __restrict__ bias,   // [6H]
    float* __restrict__ out)          // hseq [B,T,H] then h_last [B,H]
{
  extern __shared__ __align__(1024) char smem[];
  const uint32_t sb = smem_u32(smem);
  const int tid = threadIdx.x;
  const int w   = tid >> 5;
  const int l   = tid & 31;
  const int c   = blockIdx.x;
  const int cb  = c * 8;

  for (int idx = tid; idx < 24 * 1024; idx += 256) {
    int n = idx >> 10;
    int k = idx & 1023;
    float wv = Wh[(size_t)k * G3 + (n >> 3) * Hdim + cb + (n & 7)];
    __nv_bfloat16 hi = __float2bfloat16_rn(wv);
    __nv_bfloat16 lo = __float2bfloat16_rn(wv - __bfloat162float(hi));
    int row = n & 7;
    uint32_t off = (uint32_t)(((k >> 6) * 3 + (n >> 3)) * 1024 + row * 128 +
                              ((((k & 63) * 2)) ^ (row << 4)));
    *(__nv_bfloat16*)(smem + OFF_BHI + off) = hi;
    *(__nv_bfloat16*)(smem + OFF_BLO + off) = lo;
  }
  __syncthreads();

  const int arow = w * 16 + (l & 7) + ((l >> 3) & 1) * 8;
  const uint32_t QA = ((uint32_t)((l >> 4) & 1) * 16) ^ (((uint32_t)arow & 7) << 4);
  const uint32_t PAr = (uint32_t)arow * 128;
  const int brow = l & 7;
  const int bnt  = (l >> 4) & 1;
  const uint32_t QB = ((uint32_t)((l >> 3) & 1) * 16) ^ ((uint32_t)brow << 4);
  const uint32_t PBr = (uint32_t)bnt * 1024 + (uint32_t)brow * 128;

  const int quad = l >> 2;
  const int c0   = (l & 3) * 2;
  const int bA   = w * 16 + quad;
  const int bB   = bA + 8;

  float bh[3][2];
#pragma unroll
  for (int g = 0; g < 3; g++) {
    bh[g][0] = bias[G3 + g * Hdim + cb + c0];
    bh[g][1] = bias[G3 + g * Hdim + cb + c0 + 1];
  }

  float hreg[2][2] = {{0.f, 0.f}, {0.f, 0.f}};

  for (int t = 0; t < Tdim; t++) {
    float2 fi[2][3];
#pragma unroll
    for (int bi = 0; bi < 2; bi++) {
      const int b = bi ? bB : bA;
      const float* fb = g_fi + ((size_t)t * Bdim + b) * G3 + cb + c0;
#pragma unroll
      for (int g = 0; g < 3; g++)
        fi[bi][g] = __ldg((const float2*)(fb + g * Hdim));
    }

    float d[3][4];
#pragma unroll
    for (int g = 0; g < 3; g++)
#pragma unroll
      for (int j = 0; j < 4; j++) d[g][j] = 0.0f;

    if (t > 0) {
      uint4 ph[4], pl[4];
#pragma unroll
      for (int q4 = 0; q4 < 4; q4++) {
        int idx = tid + q4 * 256;
        int b = idx >> 3, q = idx & 7;
        ph[q4] = *(const uint4*)(g_hh + (size_t)b * Hdim + q * 8);
        pl[q4] = *(const uint4*)(g_hl + (size_t)b * Hdim + q * 8);
      }
#pragma unroll
      for (int q4 = 0; q4 < 4; q4++) {
        int idx = tid + q4 * 256;
        int b = idx >> 3, q = idx & 7;
        uint32_t so = (uint32_t)b * 128 + (((uint32_t)q * 16) ^ (((uint32_t)b & 7) << 4));
        *(uint4*)(smem + A_HI(0) + so) = ph[q4];
        *(uint4*)(smem + A_LO(0) + so) = pl[q4];
      }
      __syncthreads();
#pragma unroll
      for (int q4 = 0; q4 < 4; q4++) {
        int idx = tid + q4 * 256;
        int b = idx >> 3, q = idx & 7;
        ph[q4] = *(const uint4*)(g_hh + (size_t)b * Hdim + 64 + q * 8);
        pl[q4] = *(const uint4*)(g_hl + (size_t)b * Hdim + 64 + q * 8);
      }

      for (int i = 0; i < 16; i++) {
        const int buf = i & 1;
        const uint32_t pa_hi = sb + A_HI(buf) + PAr;
        const uint32_t pa_lo = sb + A_LO(buf) + PAr;
        const uint32_t pb_hi = sb + OFF_BHI + (uint32_t)i * 3072 + PBr;
        const uint32_t pb_lo = sb + OFF_BLO + (uint32_t)i * 3072 + PBr;
        const uint32_t pb2_hi = sb + OFF_BHI + (uint32_t)i * 3072 + 2048 + (uint32_t)brow * 128;
        const uint32_t pb2_lo = sb + OFF_BLO + (uint32_t)i * 3072 + 2048 + (uint32_t)brow * 128;

#pragma unroll
        for (int kk = 0; kk < 4; kk++) {
          const uint32_t ao = ((uint32_t)kk * 32) ^ QA;
          const uint32_t bo = ((uint32_t)kk * 32) ^ QB;
          uint32_t Ah[4], Al[4], Bh[4], Bl[4], B2h[2], B2l[2];
          LDSM_X4(Ah, pa_hi + ao);
          LDSM_X4(Al, pa_lo + ao);
          LDSM_X4(Bh, pb_hi + bo);
          LDSM_X4(Bl, pb_lo + bo);
          LDSM_X2(B2h, pb2_hi + bo);
          LDSM_X2(B2l, pb2_lo + bo);
          mma16816(d[0], Ah, Bh[0], Bh[1]);
          mma16816(d[0], Ah, Bl[0], Bl[1]);
          mma16816(d[0], Al, Bh[0], Bh[1]);
          mma16816(d[1], Ah, Bh[2], Bh[3]);
          mma16816(d[1], Ah, Bl[2], Bl[3]);
          mma16816(d[1], Al, Bh[2], Bh[3]);
          mma16816(d[2], Ah, B2h[0], B2h[1]);
          mma16816(d[2], Ah, B2l[0], B2l[1]);
          mma16816(d[2], Al, B2h[0], B2h[1]);
        }

        if (i < 15) {
#pragma unroll
          for (int q4 = 0; q4 < 4; q4++) {
            int idx = tid + q4 * 256;
            int b = idx >> 3, q = idx & 7;
            uint32_t so = (uint32_t)b * 128 + (((uint32_t)q * 16) ^ (((uint32_t)b & 7) << 4));
            *(uint4*)(smem + A_HI(buf ^ 1) + so) = ph[q4];
            *(uint4*)(smem + A_LO(buf ^ 1) + so) = pl[q4];
          }
          if (i < 14) {
            const int kb = (i + 2) * 64;
#pragma unroll
            for (int q4 = 0; q4 < 4; q4++) {
              int idx = tid + q4 * 256;
              int b = idx >> 3, q = idx & 7;
              ph[q4] = *(const uint4*)(g_hh + (size_t)b * Hdim + kb + q * 8);
              pl[q4] = *(const uint4*)(g_hl + (size_t)b * Hdim + kb + q * 8);
            }
          }
        }
        __syncthreads();
      }
    }

#pragma unroll
    for (int bi = 0; bi < 2; bi++) {
      const int b = bi ? bB : bA;
      float hv[2];
#pragma unroll
      for (int j = 0; j < 2; j++) {
        float fr = (j ? fi[bi][0].y : fi[bi][0].x);
        float fz = (j ? fi[bi][1].y : fi[bi][1].x);
        float fn = (j ? fi[bi][2].y : fi[bi][2].x);
        float rr = sigmoidf_fast(fr + d[0][bi * 2 + j] + bh[0][j]);
        float zz = sigmoidf_fast(fz + d[1][bi * 2 + j] + bh[1][j]);
        float nn = tanhf(fn + rr * (d[2][bi * 2 + j] + bh[2][j]));
        hv[j] = (1.0f - zz) * nn + zz * hreg[bi][j];
        hreg[bi][j] = hv[j];
      }
      *(float2*)(out + ((size_t)b * Tdim + t) * Hdim + cb + c0) = make_float2(hv[0], hv[1]);
      __nv_bfloat162 h2 = __floats2bfloat162_rn(hv[0], hv[1]);
      float l0 = hv[0] - __bfloat162float(__float2bfloat16_rn(hv[0]));
      float l1 = hv[1] - __bfloat162float(__float2bfloat16_rn(hv[1]));
      __nv_bfloat162 l2 = __floats2bfloat162_rn(l0, l1);
      *(__nv_bfloat162*)(g_hh + (size_t)b * Hdim + cb + c0) = h2;
      *(__nv_bfloat162*)(g_hl + (size_t)b * Hdim + cb + c0) = l2;
      if (t == Tdim - 1) {
        *(float2*)(out + (size_t)Bdim * Tdim * Hdim + (size_t)b * Hdim + cb + c0) =
            make_float2(hv[0], hv[1]);
      }
    }

    if (t < Tdim - 1) {
      __syncthreads();
      if (tid == 0) {
        bar_arrive(&g_bar[t]);
        while (bar_peek(&g_bar[t]) < NCTA) { __nanosleep(32); }
      }
      __syncthreads();
    }
  }
}

// =====================================================================
extern "C" void kernel_launch(void* const* d_in, const int* in_sizes, int n_in,
                              void* d_out, int out_size) {
  (void)in_sizes; (void)n_in; (void)out_size;
  const float* inputs = (const float*)d_in[0];
  const float* W_in   = (const float*)d_in[1];
  const float* W_h    = (const float*)d_in[2];
  const float* bias   = (const float*)d_in[3];
  float* out = (float*)d_out;

  static int attr_set = 0;
  if (!attr_set) {
    cudaFuncSetAttribute(recurrence_kernel,
                         cudaFuncAttributeMaxDynamicSharedMemorySize, SMEM_REC);
    cudaFuncSetAttribute(gemm_fi_mma_kernel,
                         cudaFuncAttributeMaxDynamicSharedMemorySize, PA_SMEM);
    attr_set = 1;
  }

  reset_kernel<<<1, Tdim>>>();
  conv_in_kernel<<<(int)((size_t)MTOT * Idim / 2 / 256), 256>>>(inputs);
  {
    dim3 grid(G3 / 32, Idim / 32);       // (96, 16)
    conv_w_kernel<<<grid, 256>>>(W_in);
  }
  {
    dim3 grid(G3 / 128, MTOT / 128);     // (24, 512)
    gemm_fi_mma_kernel<<<grid, 256, PA_SMEM>>>(bias);
  }
  recurrence_kernel<<<NCTA, 256, SMEM_REC>>>(W_h, bias, out);
}

// round 16
// speedup vs baseline: 3.6444x; 1.1714x over previous
#include <cuda_runtime.h>
#include <cuda_bf16.h>
#include <cstdint>

// GRU dims
#define Bdim  128
#define Tdim  512
#define Idim  512
#define Hdim  1024
#define G3    3072
#define MTOT  65536
#define NCTA  128

// ---- recurrence smem layout (bytes): W 96KB + A ring 3x32KB ----
#define R_BHI   0
#define R_BLO   49152
#define R_A     98304
#define R_AH(s) (R_A + (s) * 32768)
#define R_AL(s) (R_A + (s) * 32768 + 16384)
#define SMEM_REC (R_A + 3 * 32768)          // 196608

// ---- phase A smem layout ----
#define PA_AH(buf) ((buf) * 65536 + 0)
#define PA_AL(buf) ((buf) * 65536 + 16384)
#define PA_BH(buf) ((buf) * 65536 + 32768)
#define PA_BL(buf) ((buf) * 65536 + 49152)
#define PA_SMEM    131072

// Scratch (static __device__ — no allocations allowed)
__device__ float g_fi[(size_t)MTOT * G3];               // [T][B][3H]
__device__ __nv_bfloat16 g_ah[(size_t)MTOT * Idim];     // inputs hi
__device__ __nv_bfloat16 g_al[(size_t)MTOT * Idim];     // inputs lo
__device__ __nv_bfloat16 g_wh[(size_t)G3 * Idim];       // W_in^T hi  [n][k]
__device__ __nv_bfloat16 g_wl[(size_t)G3 * Idim];       // W_in^T lo
__device__ __nv_bfloat16 g_hh[(size_t)Bdim * Hdim];     // h hi
__device__ __nv_bfloat16 g_hl[(size_t)Bdim * Hdim];     // h lo
__device__ unsigned g_bar[Tdim];

__device__ __forceinline__ float sigmoidf_fast(float x) {
  return 1.0f / (1.0f + __expf(-x));
}

// ---------- grid barrier ----------
__device__ __forceinline__ void bar_arrive(unsigned* p) {
  asm volatile("red.release.gpu.global.add.u32 [%0], 1;" :: "l"(p) : "memory");
}
__device__ __forceinline__ unsigned bar_peek(const unsigned* p) {
  unsigned v;
  asm volatile("ld.acquire.gpu.global.u32 %0, [%1];" : "=r"(v) : "l"(p) : "memory");
  return v;
}

// ---------- HMMA / ldmatrix / cp.async ----------
__device__ __forceinline__ uint32_t smem_u32(const void* p) {
  uint32_t a;
  asm("{ .reg .u64 t; cvta.to.shared.u64 t, %1; cvt.u32.u64 %0, t; }" : "=r"(a) : "l"(p));
  return a;
}
#define LDSM_X4(r, a) \
  asm volatile("ldmatrix.sync.aligned.m8n8.x4.shared.b16 {%0,%1,%2,%3}, [%4];" \
    : "=r"((r)[0]), "=r"((r)[1]), "=r"((r)[2]), "=r"((r)[3]) : "r"(a))
#define LDSM_X2(r, a) \
  asm volatile("ldmatrix.sync.aligned.m8n8.x2.shared.b16 {%0,%1}, [%2];" \
    : "=r"((r)[0]), "=r"((r)[1]) : "r"(a))

__device__ __forceinline__ void mma16816(float* d, const uint32_t* a,
                                         uint32_t b0, uint32_t b1) {
  asm volatile(
    "mma.sync.aligned.m16n8k16.row.col.f32.bf16.bf16.f32 "
    "{%0,%1,%2,%3}, {%4,%5,%6,%7}, {%8,%9}, {%0,%1,%2,%3};"
    : "+f"(d[0]), "+f"(d[1]), "+f"(d[2]), "+f"(d[3])
    : "r"(a[0]), "r"(a[1]), "r"(a[2]), "r"(a[3]), "r"(b0), "r"(b1));
}

__device__ __forceinline__ void cp16(uint32_t dst, const void* src) {
  asm volatile("cp.async.cg.shared.global [%0], [%1], 16;" :: "r"(dst), "l"(src));
}
#define CP_COMMIT() asm volatile("cp.async.commit_group;" ::: "memory")
#define CP_WAIT0()  asm volatile("cp.async.wait_group 0;" ::: "memory")
#define CP_WAIT1()  asm volatile("cp.async.wait_group 1;" ::: "memory")

// =====================================================================
__global__ void reset_kernel() { g_bar[threadIdx.x] = 0u; }

// =====================================================================
// Convert inputs -> bf16 hi/lo
// =====================================================================
__global__ void __launch_bounds__(256) conv_in_kernel(const float* __restrict__ x) {
  size_t i = ((size_t)blockIdx.x * 256 + threadIdx.x) * 2;
  float2 v = *(const float2*)(x + i);
  __nv_bfloat16 h0 = __float2bfloat16_rn(v.x);
  __nv_bfloat16 h1 = __float2bfloat16_rn(v.y);
  __nv_bfloat16 l0 = __float2bfloat16_rn(v.x - __bfloat162float(h0));
  __nv_bfloat16 l1 = __float2bfloat16_rn(v.y - __bfloat162float(h1));
  *(__nv_bfloat162*)(g_ah + i) = __nv_bfloat162(h0, h1);
  *(__nv_bfloat162*)(g_al + i) = __nv_bfloat162(l0, l1);
}

// =====================================================================
// Convert + transpose W_in [K=512][N=3072] -> g_wh/g_wl [N][K] hi/lo
// =====================================================================
__global__ void __launch_bounds__(256) conv_w_kernel(const float* __restrict__ W) {
  __shared__ float tile[32][33];
  const int tx = threadIdx.x & 31;
  const int ty = threadIdx.x >> 5;
  const int kb = blockIdx.y * 32;
  const int nb = blockIdx.x * 32;
#pragma unroll
  for (int i = 0; i < 4; i++)
    tile[ty + i * 8][tx] = W[(size_t)(kb + ty + i * 8) * G3 + nb + tx];
  __syncthreads();
#pragma unroll
  for (int i = 0; i < 4; i++) {
    int n = nb + ty + i * 8;
    int k = kb + tx;
    float v = tile[tx][ty + i * 8];
    __nv_bfloat16 h = __float2bfloat16_rn(v);
    g_wh[(size_t)n * Idim + k] = h;
    g_wl[(size_t)n * Idim + k] = __float2bfloat16_rn(v - __bfloat162float(h));
  }
}

// =====================================================================
// Phase A (HMMA): g_fi[t][b][n] = inputs@W_in + bias_in, split-bf16 3-pass.
// =====================================================================
__global__ void __launch_bounds__(256) gemm_fi_mma_kernel(
    const float* __restrict__ bias)
{
  extern __shared__ __align__(1024) char smem[];
  const uint32_t sb = smem_u32(smem);
  const int tid = threadIdx.x;
  const int w   = tid >> 5;
  const int l   = tid & 31;
  const int mw  = w & 1;
  const int nw  = w >> 1;
  const int bm  = blockIdx.y * 128;
  const int bn  = blockIdx.x * 128;

  const int srow = tid >> 3;
  const int sq   = tid & 7;
  const uint32_t soff0 = (uint32_t)srow * 128 + (((uint32_t)sq * 16) ^ (((uint32_t)srow & 7) << 4));

  float acc[4][4][4];
#pragma unroll
  for (int mt = 0; mt < 4; mt++)
#pragma unroll
    for (int nt = 0; nt < 4; nt++)
#pragma unroll
      for (int j = 0; j < 4; j++) acc[mt][nt][j] = 0.0f;

  const uint32_t PAr = (uint32_t)(((l & 7) + ((l >> 3) & 1) * 8)) * 128;
  const uint32_t QA  = ((uint32_t)((l >> 4) & 1) * 16) ^ (((uint32_t)l & 7) << 4);
  const uint32_t PBr = (uint32_t)(((l & 7) + ((l >> 4) & 1) * 8)) * 128;
  const uint32_t QB  = ((uint32_t)((l >> 3) & 1) * 16) ^ (((uint32_t)l & 7) << 4);

  auto stage = [&](int buf, int kb) {
#pragma unroll
    for (int q4 = 0; q4 < 4; q4++) {
      int row = srow + q4 * 32;
      uint32_t so = soff0 + (uint32_t)q4 * 32 * 128;
      const size_t asrc = (size_t)(bm + row) * Idim + kb + sq * 8;
      const size_t bsrc = (size_t)(bn + row) * Idim + kb + sq * 8;
      cp16(sb + PA_AH(buf) + so, g_ah + asrc);
      cp16(sb + PA_AL(buf) + so, g_al + asrc);
      cp16(sb + PA_BH(buf) + so, g_wh + bsrc);
      cp16(sb + PA_BL(buf) + so, g_wl + bsrc);
    }
  };

  stage(0, 0);
  CP_COMMIT();
  CP_WAIT0();
  __syncthreads();

  for (int kt = 0; kt < 8; kt++) {
    const int buf = kt & 1;
    if (kt < 7) { stage(buf ^ 1, (kt + 1) * 64); CP_COMMIT(); }

    const uint32_t ah_b = sb + PA_AH(buf) + (uint32_t)(mw * 64) * 128 + PAr;
    const uint32_t al_b = sb + PA_AL(buf) + (uint32_t)(mw * 64) * 128 + PAr;
    const uint32_t bh_b = sb + PA_BH(buf) + (uint32_t)(nw * 32) * 128 + PBr;
    const uint32_t bl_b = sb + PA_BL(buf) + (uint32_t)(nw * 32) * 128 + PBr;

#pragma unroll
    for (int kk = 0; kk < 4; kk++) {
      const uint32_t ao = ((uint32_t)kk * 32) ^ QA;
      const uint32_t bo = ((uint32_t)kk * 32) ^ QB;
      uint32_t Ah[4][4], Al[4][4];
#pragma unroll
      for (int mt = 0; mt < 4; mt++) {
        LDSM_X4(Ah[mt], ah_b + (uint32_t)(mt * 16) * 128 + ao);
        LDSM_X4(Al[mt], al_b + (uint32_t)(mt * 16) * 128 + ao);
      }
#pragma unroll
      for (int ntp = 0; ntp < 2; ntp++) {
        uint32_t Bh[4], Bl[4];
        LDSM_X4(Bh, bh_b + (uint32_t)(ntp * 16) * 128 + bo);
        LDSM_X4(Bl, bl_b + (uint32_t)(ntp * 16) * 128 + bo);
#pragma unroll
        for (int mt = 0; mt < 4; mt++) {
          mma16816(acc[mt][ntp * 2],     Ah[mt], Bh[0], Bh[1]);
          mma16816(acc[mt][ntp * 2 + 1], Ah[mt], Bh[2], Bh[3]);
          mma16816(acc[mt][ntp * 2],     Ah[mt], Bl[0], Bl[1]);
          mma16816(acc[mt][ntp * 2 + 1], Ah[mt], Bl[2], Bl[3]);
          mma16816(acc[mt][ntp * 2],     Al[mt], Bh[0], Bh[1]);
          mma16816(acc[mt][ntp * 2 + 1], Al[mt], Bh[2], Bh[3]);
        }
      }
    }

    if (kt < 7) CP_WAIT0();
    __syncthreads();
  }

  const int quad = l >> 2;
  const int cq   = (l & 3) * 2;
#pragma unroll
  for (int nt = 0; nt < 4; nt++) {
    const int col = bn + nw * 32 + nt * 8 + cq;
    const float2 bv = *(const float2*)(bias + col);
#pragma unroll
    for (int mt = 0; mt < 4; mt++) {
      int m0 = bm + mw * 64 + mt * 16 + quad;
#pragma unroll
      for (int half = 0; half < 2; half++) {
        int m  = m0 + half * 8;
        int b  = m >> 9;
        int tt = m & (Tdim - 1);
        *(float2*)(g_fi + ((size_t)tt * Bdim + b) * G3 + col) =
            make_float2(acc[mt][nt][half * 2] + bv.x, acc[mt][nt][half * 2 + 1] + bv.y);
      }
    }
  }
}

// =====================================================================
// Persistent HMMA recurrence: 128 CTAs x 256 threads.
// cp.async 3-stage ring for h tiles; W resident in smem.
// =====================================================================
__global__ void __launch_bounds__(256, 1) recurrence_kernel(
    const float* __restrict__ Wh,     // [Hdim, G3]
    const float* __restrict__ bias,   // [6H]
    float* __restrict__ out)          // hseq [B,T,H] then h_last [B,H]
{
  extern __shared__ __align__(1024) char smem[];
  const uint32_t sb = smem_u32(smem);
  const int tid = threadIdx.x;
  const int w   = tid >> 5;
  const int l   = tid & 31;
  const int c   = blockIdx.x;
  const int cb  = c * 8;

  // ---- Stage W slice (transposed, split hi/lo) once ----
  for (int idx = tid; idx < 24 * 1024; idx += 256) {
    int n = idx >> 10;
    int k = idx & 1023;
    float wv = Wh[(size_t)k * G3 + (n >> 3) * Hdim + cb + (n & 7)];
    __nv_bfloat16 hi = __float2bfloat16_rn(wv);
    __nv_bfloat16 lo = __float2bfloat16_rn(wv - __bfloat162float(hi));
    int row = n & 7;
    uint32_t off = (uint32_t)(((k >> 6) * 3 + (n >> 3)) * 1024 + row * 128 +
                              ((((k & 63) * 2)) ^ (row << 4)));
    *(__nv_bfloat16*)(smem + R_BHI + off) = hi;
    *(__nv_bfloat16*)(smem + R_BLO + off) = lo;
  }
  __syncthreads();

  const int arow = w * 16 + (l & 7) + ((l >> 3) & 1) * 8;
  const uint32_t QA = ((uint32_t)((l >> 4) & 1) * 16) ^ (((uint32_t)arow & 7) << 4);
  const uint32_t PAr = (uint32_t)arow * 128;
  const int brow = l & 7;
  const int bnt  = (l >> 4) & 1;
  const uint32_t QB = ((uint32_t)((l >> 3) & 1) * 16) ^ ((uint32_t)brow << 4);
  const uint32_t PBr = (uint32_t)bnt * 1024 + (uint32_t)brow * 128;

  const int srow = tid >> 3;
  const int sq   = tid & 7;

  const int quad = l >> 2;
  const int c0   = (l & 3) * 2;
  const int bA   = w * 16 + quad;
  const int bB   = bA + 8;

  float bh[3][2];
#pragma unroll
  for (int g = 0; g < 3; g++) {
    bh[g][0] = bias[G3 + g * Hdim + cb + c0];
    bh[g][1] = bias[G3 + g * Hdim + cb + c0 + 1];
  }

  float hreg[2][2] = {{0.f, 0.f}, {0.f, 0.f}};

  for (int t = 0; t < Tdim; t++) {
    float2 fi[2][3];
#pragma unroll
    for (int bi = 0; bi < 2; bi++) {
      const int b = bi ? bB : bA;
      const float* fb = g_fi + ((size_t)t * Bdim + b) * G3 + cb + c0;
#pragma unroll
      for (int g = 0; g < 3; g++)
        fi[bi][g] = __ldg((const float2*)(fb + g * Hdim));
    }

    float d[3][4];
#pragma unroll
    for (int g = 0; g < 3; g++)
#pragma unroll
      for (int j = 0; j < 4; j++) d[g][j] = 0.0f;

    if (t > 0) {
      auto stageA = [&](int slot, int tile) {
        const int kb = tile * 64;
#pragma unroll
        for (int q4 = 0; q4 < 4; q4++) {
          int b = srow + q4 * 32;
          uint32_t so = (uint32_t)b * 128 + (((uint32_t)sq * 16) ^ (((uint32_t)b & 7) << 4));
          cp16(sb + R_AH(slot) + so, g_hh + (size_t)b * Hdim + kb + sq * 8);
          cp16(sb + R_AL(slot) + so, g_hl + (size_t)b * Hdim + kb + sq * 8);
        }
      };

      // prologue: tiles 0 and 1 in flight
      stageA(0, 0); CP_COMMIT();
      stageA(1, 1); CP_COMMIT();

      for (int i = 0; i < 16; i++) {
        const int slot = i % 3;
        // wait for tile i: with tile i+1 still in flight use wait_group 1
        if (i < 15) CP_WAIT1(); else CP_WAIT0();
        __syncthreads();

        const uint32_t pa_hi = sb + R_AH(slot) + PAr;
        const uint32_t pa_lo = sb + R_AL(slot) + PAr;
        const uint32_t pb_hi = sb + R_BHI + (uint32_t)i * 3072 + PBr;
        const uint32_t pb_lo = sb + R_BLO + (uint32_t)i * 3072 + PBr;
        const uint32_t pb2_hi = sb + R_BHI + (uint32_t)i * 3072 + 2048 + (uint32_t)brow * 128;
        const uint32_t pb2_lo = sb + R_BLO + (uint32_t)i * 3072 + 2048 + (uint32_t)brow * 128;

#pragma unroll
        for (int kk = 0; kk < 4; kk++) {
          const uint32_t ao = ((uint32_t)kk * 32) ^ QA;
          const uint32_t bo = ((uint32_t)kk * 32) ^ QB;
          uint32_t Ah[4], Al[4], Bh[4], Bl[4], B2h[2], B2l[2];
          LDSM_X4(Ah, pa_hi + ao);
          LDSM_X4(Al, pa_lo + ao);
          LDSM_X4(Bh, pb_hi + bo);
          LDSM_X4(Bl, pb_lo + bo);
          LDSM_X2(B2h, pb2_hi + bo);
          LDSM_X2(B2l, pb2_lo + bo);
          // interleaved accumulators: reuse distance 3
          mma16816(d[0], Ah, Bh[0], Bh[1]);
          mma16816(d[1], Ah, Bh[2], Bh[3]);
          mma16816(d[2], Ah, B2h[0], B2h[1]);
          mma16816(d[0], Ah, Bl[0], Bl[1]);
          mma16816(d[1], Ah, Bl[2], Bl[3]);
          mma16816(d[2], Ah, B2l[0], B2l[1]);
          mma16816(d[0], Al, Bh[0], Bh[1]);
          mma16816(d[1], Al, Bh[2], Bh[3]);
          mma16816(d[2], Al, B2h[0], B2h[1]);
        }

        // sync before reusing this slot for tile i+3 (issued next iteration+)
        __syncthreads();
        // issue tile i+2 into slot (i+2)%3 (distinct from current & next slot)
        if (i < 14) { stageA((i + 2) % 3, i + 2); CP_COMMIT(); }
      }
    }

#pragma unroll
    for (int bi = 0; bi < 2; bi++) {
      const int b = bi ? bB : bA;
      float hv[2];
#pragma unroll
      for (int j = 0; j < 2; j++) {
        float fr = (j ? fi[bi][0].y : fi[bi][0].x);
        float fz = (j ? fi[bi][1].y : fi[bi][1].x);
        float fn = (j ? fi[bi][2].y : fi[bi][2].x);
        float rr = sigmoidf_fast(fr + d[0][bi * 2 + j] + bh[0][j]);
        float zz = sigmoidf_fast(fz + d[1][bi * 2 + j] + bh[1][j]);
        float nn = tanhf(fn + rr * (d[2][bi * 2 + j] + bh[2][j]));
        hv[j] = (1.0f - zz) * nn + zz * hreg[bi][j];
        hreg[bi][j] = hv[j];
      }
      *(float2*)(out + ((size_t)b * Tdim + t) * Hdim + cb + c0) = make_float2(hv[0], hv[1]);
      __nv_bfloat162 h2 = __floats2bfloat162_rn(hv[0], hv[1]);
      float l0 = hv[0] - __bfloat162float(__float2bfloat16_rn(hv[0]));
      float l1 = hv[1] - __bfloat162float(__float2bfloat16_rn(hv[1]));
      __nv_bfloat162 l2 = __floats2bfloat162_rn(l0, l1);
      *(__nv_bfloat162*)(g_hh + (size_t)b * Hdim + cb + c0) = h2;
      *(__nv_bfloat162*)(g_hl + (size_t)b * Hdim + cb + c0) = l2;
      if (t == Tdim - 1) {
        *(float2*)(out + (size_t)Bdim * Tdim * Hdim + (size_t)b * Hdim + cb + c0) =
            make_float2(hv[0], hv[1]);
      }
    }

    if (t < Tdim - 1) {
      __syncthreads();
      if (tid == 0) {
        bar_arrive(&g_bar[t]);
        while (bar_peek(&g_bar[t]) < NCTA) { __nanosleep(32); }
      }
      __syncthreads();
    }
  }
}

// =====================================================================
extern "C" void kernel_launch(void* const* d_in, const int* in_sizes, int n_in,
                              void* d_out, int out_size) {
  (void)in_sizes; (void)n_in; (void)out_size;
  const float* inputs = (const float*)d_in[0];
  const float* W_in   = (const float*)d_in[1];
  const float* W_h    = (const float*)d_in[2];
  const float* bias   = (const float*)d_in[3];
  float* out = (float*)d_out;

  static int attr_set = 0;
  if (!attr_set) {
    cudaFuncSetAttribute(recurrence_kernel,
                         cudaFuncAttributeMaxDynamicSharedMemorySize, SMEM_REC);
    cudaFuncSetAttribute(gemm_fi_mma_kernel,
                         cudaFuncAttributeMaxDynamicSharedMemorySize, PA_SMEM);
    attr_set = 1;
  }

  reset_kernel<<<1, Tdim>>>();
  conv_in_kernel<<<(int)((size_t)MTOT * Idim / 2 / 256), 256>>>(inputs);
  {
    dim3 grid(G3 / 32, Idim / 32);
    conv_w_kernel<<<grid, 256>>>(W_in);
  }
  {
    dim3 grid(G3 / 128, MTOT / 128);
    gemm_fi_mma_kernel<<<grid, 256, PA_SMEM>>>(bias);
  }
  recurrence_kernel<<<NCTA, 256, SMEM_REC>>>(W_h, bias, out);
}